// round 7
// baseline (speedup 1.0000x reference)
#include <cuda_runtime.h>
#include <cuda_bf16.h>
#include <math.h>
#include <stdint.h>

// Problem constants
#define B   8
#define NQ  300
#define NK  4096
#define E   256
#define H   8
#define D   32
#define FF  2048
#define LAYERS 6
#define ATTN_SCALE 0.17677669529663687f

#define TQ 32      // CA query tile
#define CK 128     // CA key chunk

#define MQ_ROWS (B * NQ)   // 2400
#define MK_ROWS (B * NK)   // 32768

#if defined(__CUDA_ARCH_SPECIFIC__) || defined(__CUDA_ARCH_FEAT_SM103_ALL) || defined(__CUDA_ARCH_FEAT_SM100_ALL)
#define HAS_TC 1
#else
#define HAS_TC 0
#endif

// ---------------- fp32 scratch ----------------
__device__ float g_t[MQ_ROWS * E];
__device__ float g_qkv[MQ_ROWS * 3 * E];
__device__ float g_proj[MQ_ROWS * E];
__device__ float g_q[MQ_ROWS * E];
__device__ float g_k[MK_ROWS * E];
__device__ float g_v[MK_ROWS * E];

// ---------------- bf16 hi/lo scratch ----------------
#define OFF_WQKV 0
#define OFF_WO   1179648
#define OFF_WQ   1572864
#define OFF_WK   1966080
#define OFF_WV   2359296
#define OFF_WCO  2752512
#define OFF_W1   3145728
#define OFF_W2   6291456
#define W_TOTAL  9437184

__device__ __nv_bfloat16 g_whi[W_TOTAL];
__device__ __nv_bfloat16 g_wlo[W_TOTAL];
__device__ __nv_bfloat16 g_thi[MQ_ROWS * E],  g_tlo[MQ_ROWS * E];
__device__ __nv_bfloat16 g_ahi[MQ_ROWS * E],  g_alo[MQ_ROWS * E];
__device__ __nv_bfloat16 g_mhi[MK_ROWS * E],  g_mlo[MK_ROWS * E];
__device__ __nv_bfloat16 g_fhi[MQ_ROWS * FF], g_flo[MQ_ROWS * FF];

// ================= PTX helpers =================
__device__ __forceinline__ uint32_t smem_u32(const void* p) {
    uint32_t a;
    asm("{ .reg .u64 t; cvta.to.shared.u64 t, %1; cvt.u32.u64 %0, t; }" : "=r"(a) : "l"(p));
    return a;
}

#if HAS_TC
__device__ __forceinline__ uint32_t elect_one() {
    uint32_t pred;
    asm volatile("{.reg .pred p; elect.sync _|p, 0xFFFFFFFF; selp.b32 %0, 1, 0, p;}" : "=r"(pred));
    return pred;
}
#define TC_ALLOC(sm, n)  asm volatile("tcgen05.alloc.cta_group::1.sync.aligned.shared::cta.b32 [%0], %1;" :: "r"((uint32_t)(sm)), "r"((uint32_t)(n)) : "memory")
#define TC_DEALLOC(t, n) asm volatile("tcgen05.dealloc.cta_group::1.sync.aligned.b32 %0, %1;" :: "r"(t), "r"((uint32_t)(n)))
#define TC_RELINQ()      asm volatile("tcgen05.relinquish_alloc_permit.cta_group::1.sync.aligned;")
#define TC_COMMIT(mb)    asm volatile("tcgen05.commit.cta_group::1.mbarrier::arrive::one.shared::cluster.b64 [%0];" :: "r"((uint32_t)(mb)) : "memory")
#define TC_WAIT_LD()     asm volatile("tcgen05.wait::ld.sync.aligned;" ::: "memory")
#define TC_FENCE_AFTER() asm volatile("tcgen05.fence::after_thread_sync;" ::: "memory")
#define FENCE_ASYNC()    asm volatile("fence.proxy.async.shared::cta;" ::: "memory")
#define MBAR_INIT(mb, c) asm volatile("mbarrier.init.shared.b64 [%0], %1;" :: "r"((uint32_t)(mb)), "r"((uint32_t)(c)) : "memory")

#define MBAR_WAIT(mb, ph) do { \
    uint32_t _m = (uint32_t)(mb), _p = (uint32_t)(ph), _d; \
    asm volatile("{.reg .pred p; mbarrier.try_wait.parity.acquire.cta.shared::cta.b64 p, [%1], %2; selp.b32 %0, 1, 0, p;}" \
        : "=r"(_d) : "r"(_m), "r"(_p) : "memory"); \
    if (!_d) { \
        asm volatile("{.reg .pred P1; WL_%=: mbarrier.try_wait.parity.acquire.cta.shared::cta.b64 P1, [%0], %1, 0x989680;" \
            "@P1 bra.uni WD_%=; bra.uni WL_%=; WD_%=: }" :: "r"(_m), "r"(_p) : "memory"); \
    } \
} while (0)

#define TC_LD_X32(r, addr) \
    asm volatile("tcgen05.ld.sync.aligned.32x32b.x32.b32 " \
        "{%0,%1,%2,%3,%4,%5,%6,%7,%8,%9,%10,%11,%12,%13,%14,%15," \
        "%16,%17,%18,%19,%20,%21,%22,%23,%24,%25,%26,%27,%28,%29,%30,%31}, [%32];" \
        : "=r"((r)[0]),"=r"((r)[1]),"=r"((r)[2]),"=r"((r)[3]),"=r"((r)[4]),"=r"((r)[5]),"=r"((r)[6]),"=r"((r)[7]), \
          "=r"((r)[8]),"=r"((r)[9]),"=r"((r)[10]),"=r"((r)[11]),"=r"((r)[12]),"=r"((r)[13]),"=r"((r)[14]),"=r"((r)[15]), \
          "=r"((r)[16]),"=r"((r)[17]),"=r"((r)[18]),"=r"((r)[19]),"=r"((r)[20]),"=r"((r)[21]),"=r"((r)[22]),"=r"((r)[23]), \
          "=r"((r)[24]),"=r"((r)[25]),"=r"((r)[26]),"=r"((r)[27]),"=r"((r)[28]),"=r"((r)[29]),"=r"((r)[30]),"=r"((r)[31]) \
        : "r"(addr))

__device__ __forceinline__ void mma_f16_ss(uint32_t d, uint64_t a, uint64_t b,
                                           uint32_t idesc, bool acc) {
    uint32_t e = acc ? 1u : 0u;
    asm volatile(
        "{\n\t.reg .pred p;\n\tsetp.ne.u32 p, %4, 0;\n\t"
        "tcgen05.mma.cta_group::1.kind::f16 [%0], %1, %2, %3, {%5, %5, %5, %5}, p;\n\t}"
        :: "r"(d), "l"(a), "l"(b), "r"(idesc), "r"(e), "r"(0u) : "memory");
}
#endif // HAS_TC

#define SW128(x) ((x) ^ (((x) >> 3) & 0x70))
static constexpr uint64_t DESC_BASE_SW128 =
    (uint64_t(2) << 61) | (uint64_t(1) << 46) | (uint64_t(64) << 32) | (uint64_t(1) << 16);
#define MK_DESC(a) (DESC_BASE_SW128 | ((uint64_t)((a) >> 4) & 0x3FFF))

// idesc: F32 accum, bf16 A/B, M=128, N=128
#define TC_IDESC ((1u << 4) | (1u << 7) | (1u << 10) | (16u << 17) | (8u << 24))

// ================= tcgen05 split-bf16 GEMM (double-buffered) =================
#define SMG_MBAR   0
#define SMG_TMEMP  16
#define SMG_BIAS   512
#define SMG_BUF0   1024
#define SMG_BUFSZ  65536
// within buffer: AHI 0, ALO 16384, BHI 32768, BLO 49152
#define SMG_TOTAL  (1024 + 2 * 65536 + 1024)

// C = (Ahi+Alo) @ (Whi+Wlo)^T + bias; 3-term split; optional relu; optional bf16 hi/lo output.
template <int RELU, int SPLIT>
__global__ void __launch_bounds__(128, 1) __cluster_dims__(1, 1, 1)
tc_gemm_kernel(const __nv_bfloat16* __restrict__ Ahi, const __nv_bfloat16* __restrict__ Alo,
               const __nv_bfloat16* __restrict__ Whi, const __nv_bfloat16* __restrict__ Wlo,
               const float* __restrict__ bias,
               float* __restrict__ C,
               __nv_bfloat16* __restrict__ Chi, __nv_bfloat16* __restrict__ Clo,
               int M, int N, int K) {
    extern __shared__ __align__(16) char smem_raw[];
    char* smem = (char*)((((uintptr_t)smem_raw) + 1023) & ~(uintptr_t)1023);
    const uint32_t sb = smem_u32(smem);
    const int tid = threadIdx.x;
    const int wid = tid >> 5, lane = tid & 31;
    const int n0 = blockIdx.x * 128;
    const int m0 = blockIdx.y * 128;
    (void)sb; (void)wid; (void)lane;

#if HAS_TC
    if (wid == 0) {
        TC_ALLOC(sb + SMG_TMEMP, 128);
        TC_RELINQ();
    }
    if (tid == 0) { MBAR_INIT(sb + SMG_MBAR, 1); }
    if (tid < 128) ((float*)(smem + SMG_BIAS))[tid] = bias[n0 + tid];

    const int nchunks = K >> 6;

    // stage lambda-ish macro: stage chunk kc into buffer bsel
#define STAGE_CHUNK(bsel, kc) do { \
    const int kel = (kc) * 64; \
    const uint32_t bbase = SMG_BUF0 + (bsel) * SMG_BUFSZ; \
    _Pragma("unroll") \
    for (int it = 0; it < 32; it++) { \
        int idx = it * 128 + tid; \
        int tile = idx >> 10; \
        int r = (idx >> 3) & 127; \
        int c16 = idx & 7; \
        uint4 val = make_uint4(0, 0, 0, 0); \
        if (tile < 2) { \
            int m = m0 + r; \
            if (m < M) { \
                const __nv_bfloat16* src = (tile == 0) ? Ahi : Alo; \
                val = *(const uint4*)&src[(size_t)m * K + kel + c16 * 8]; \
            } \
        } else { \
            int n = n0 + r; \
            const __nv_bfloat16* src = (tile == 2) ? Whi : Wlo; \
            val = *(const uint4*)&src[(size_t)n * K + kel + c16 * 8]; \
        } \
        uint32_t off = bbase + tile * 16384 + SW128((uint32_t)(r * 128 + c16 * 16)); \
        *(uint4*)(smem + off) = val; \
    } \
} while (0)

    STAGE_CHUNK(0, 0);
    __syncthreads();

    uint32_t tmem;
    asm volatile("ld.shared.b32 %0, [%1];" : "=r"(tmem) : "r"(sb + SMG_TMEMP));

    int phase = 0;
    for (int kc = 0; kc < nchunks; kc++) {
        const int bsel = kc & 1;
        const uint32_t bbase = sb + SMG_BUF0 + bsel * SMG_BUFSZ;
        if (wid == 0) {
            if (elect_one()) {
                FENCE_ASYNC();
                const uint64_t dAhi = MK_DESC(bbase);
                const uint64_t dAlo = MK_DESC(bbase + 16384);
                const uint64_t dBhi = MK_DESC(bbase + 32768);
                const uint64_t dBlo = MK_DESC(bbase + 49152);
                bool first = (kc == 0);
#pragma unroll
                for (int ks = 0; ks < 4; ks++)
                    mma_f16_ss(tmem, dAhi + ks * 2, dBhi + ks * 2, TC_IDESC, !(first && ks == 0));
#pragma unroll
                for (int ks = 0; ks < 4; ks++)
                    mma_f16_ss(tmem, dAhi + ks * 2, dBlo + ks * 2, TC_IDESC, true);
#pragma unroll
                for (int ks = 0; ks < 4; ks++)
                    mma_f16_ss(tmem, dAlo + ks * 2, dBhi + ks * 2, TC_IDESC, true);
                TC_COMMIT(sb + SMG_MBAR);
            }
        }
        if (kc + 1 < nchunks) {
            STAGE_CHUNK((kc + 1) & 1, kc + 1);
        }
        MBAR_WAIT(sb + SMG_MBAR, phase);
        phase ^= 1;
        __syncthreads();
    }
#undef STAGE_CHUNK

    TC_FENCE_AFTER();

    const float* bsm = (const float*)(smem + SMG_BIAS);
    const int m = m0 + wid * 32 + lane;
#pragma unroll
    for (int cc = 0; cc < 4; cc++) {
        uint32_t dr[32];
        TC_LD_X32(dr, tmem + cc * 32);
        TC_WAIT_LD();
        if (m < M) {
            const int nb = n0 + cc * 32;
            if (SPLIT) {
#pragma unroll
                for (int j2 = 0; j2 < 16; j2++) {
                    float v0 = __uint_as_float(dr[j2 * 2 + 0]) + bsm[cc * 32 + j2 * 2 + 0];
                    float v1 = __uint_as_float(dr[j2 * 2 + 1]) + bsm[cc * 32 + j2 * 2 + 1];
                    if (RELU) { v0 = fmaxf(v0, 0.f); v1 = fmaxf(v1, 0.f); }
                    __nv_bfloat16 h0 = __float2bfloat16_rn(v0);
                    __nv_bfloat16 h1 = __float2bfloat16_rn(v1);
                    __nv_bfloat16 l0 = __float2bfloat16_rn(v0 - __bfloat162float(h0));
                    __nv_bfloat16 l1 = __float2bfloat16_rn(v1 - __bfloat162float(h1));
                    *(__nv_bfloat162*)&Chi[(size_t)m * N + nb + j2 * 2] = __nv_bfloat162(h0, h1);
                    *(__nv_bfloat162*)&Clo[(size_t)m * N + nb + j2 * 2] = __nv_bfloat162(l0, l1);
                }
            } else {
                float* crow = &C[(size_t)m * N + nb];
#pragma unroll
                for (int c4 = 0; c4 < 8; c4++) {
                    float4 o;
                    o.x = __uint_as_float(dr[c4 * 4 + 0]) + bsm[cc * 32 + c4 * 4 + 0];
                    o.y = __uint_as_float(dr[c4 * 4 + 1]) + bsm[cc * 32 + c4 * 4 + 1];
                    o.z = __uint_as_float(dr[c4 * 4 + 2]) + bsm[cc * 32 + c4 * 4 + 2];
                    o.w = __uint_as_float(dr[c4 * 4 + 3]) + bsm[cc * 32 + c4 * 4 + 3];
                    if (RELU) {
                        o.x = fmaxf(o.x, 0.f); o.y = fmaxf(o.y, 0.f);
                        o.z = fmaxf(o.z, 0.f); o.w = fmaxf(o.w, 0.f);
                    }
                    *(float4*)&crow[c4 * 4] = o;
                }
            }
        }
    }

    __syncthreads();
    if (wid == 0) { TC_DEALLOC(tmem, 128); }
#else
    // generic-PTX fallback (insurance; never the loaded image on sm_103a)
    const int m = m0 + tid;
    if (m < M) {
        for (int cg = 0; cg < 4; cg++) {
            float acc[32];
#pragma unroll
            for (int j = 0; j < 32; j++) acc[j] = bias[n0 + cg * 32 + j];
            for (int k = 0; k < K; k++) {
                float a = __bfloat162float(Ahi[(size_t)m * K + k]) +
                          __bfloat162float(Alo[(size_t)m * K + k]);
#pragma unroll
                for (int j = 0; j < 32; j++) {
                    int n = n0 + cg * 32 + j;
                    float w = __bfloat162float(Whi[(size_t)n * K + k]) +
                              __bfloat162float(Wlo[(size_t)n * K + k]);
                    acc[j] += a * w;
                }
            }
#pragma unroll
            for (int j = 0; j < 32; j++) {
                float v = acc[j];
                if (RELU) v = fmaxf(v, 0.f);
                int n = n0 + cg * 32 + j;
                if (SPLIT) {
                    __nv_bfloat16 h = __float2bfloat16_rn(v);
                    Chi[(size_t)m * N + n] = h;
                    Clo[(size_t)m * N + n] = __float2bfloat16_rn(v - __bfloat162float(h));
                } else {
                    C[(size_t)m * N + n] = v;
                }
            }
        }
    }
#endif
}

// ================= mega split (all weights + memory + tgt, one launch) =================
struct SplitArgs {
    const float* src[10];
    __nv_bfloat16* hi[10];
    __nv_bfloat16* lo[10];
    float* cpy[10];
    long long cum[11];
};

__global__ void mega_split_kernel(SplitArgs a) {
    long long i = (long long)blockIdx.x * blockDim.x + threadIdx.x;
    if (i >= a.cum[10]) return;
    int s = 0;
#pragma unroll
    for (int k = 0; k < 10; k++)
        if (i >= a.cum[k + 1]) s = k + 1;
    long long off = i - a.cum[s];
    float v = a.src[s][off];
    __nv_bfloat16 h = __float2bfloat16_rn(v);
    a.hi[s][off] = h;
    a.lo[s][off] = __float2bfloat16_rn(v - __bfloat162float(h));
    if (a.cpy[s]) a.cpy[s][off] = v;
}

// ================= self-attention (writes split bf16 output) =================
__global__ void sa_attn_kernel(const float* __restrict__ qkv,
                               __nv_bfloat16* __restrict__ ohi,
                               __nv_bfloat16* __restrict__ olo) {
    const int q = blockIdx.x, h = blockIdx.y, b = blockIdx.z;
    const int tid = threadIdx.x;
    __shared__ float qs[D];
    __shared__ float sc[NQ];
    __shared__ float red[128];
    __shared__ float part[4][D];

    const float* qrow = qkv + (size_t)(b * NQ + q) * (3 * E) + h * D;
    if (tid < D) qs[tid] = qrow[tid];
    __syncthreads();

    for (int j = tid; j < NQ; j += 128) {
        const float* krow = qkv + (size_t)(b * NQ + j) * (3 * E) + E + h * D;
        float s = 0.f;
#pragma unroll
        for (int d = 0; d < D; d++) s += qs[d] * krow[d];
        sc[j] = s * ATTN_SCALE;
    }
    __syncthreads();

    float m = -INFINITY;
    for (int j = tid; j < NQ; j += 128) m = fmaxf(m, sc[j]);
    red[tid] = m;
    __syncthreads();
    for (int s = 64; s > 0; s >>= 1) {
        if (tid < s) red[tid] = fmaxf(red[tid], red[tid + s]);
        __syncthreads();
    }
    m = red[0];
    __syncthreads();

    float sum = 0.f;
    for (int j = tid; j < NQ; j += 128) {
        float e = __expf(sc[j] - m);
        sc[j] = e;
        sum += e;
    }
    red[tid] = sum;
    __syncthreads();
    for (int s = 64; s > 0; s >>= 1) {
        if (tid < s) red[tid] += red[tid + s];
        __syncthreads();
    }
    float inv = 1.f / red[0];
    __syncthreads();

    const int lane = tid & 31, grp = tid >> 5;
    float acc = 0.f;
    for (int j = grp; j < NQ; j += 4) {
        const float* vrow = qkv + (size_t)(b * NQ + j) * (3 * E) + 2 * E + h * D;
        acc += sc[j] * vrow[lane];
    }
    part[grp][lane] = acc;
    __syncthreads();
    if (tid < D) {
        float o = (part[0][tid] + part[1][tid] + part[2][tid] + part[3][tid]) * inv;
        size_t idx = (size_t)(b * NQ + q) * E + h * D + tid;
        __nv_bfloat16 hh = __float2bfloat16_rn(o);
        ohi[idx] = hh;
        olo[idx] = __float2bfloat16_rn(o - __bfloat162float(hh));
    }
}

// ================= cross-attention flash (TQ=32, writes split bf16) =================
__global__ void __launch_bounds__(256)
ca_flash_kernel(const float* __restrict__ Q,
                const float* __restrict__ Kb,
                const float* __restrict__ Vb,
                const int* __restrict__ mask,
                __nv_bfloat16* __restrict__ ohi,
                __nv_bfloat16* __restrict__ olo) {
    const int qt = blockIdx.x, h = blockIdx.y, b = blockIdx.z;
    const int tid = threadIdx.x;
    const int w = tid >> 5, lane = tid & 31;

    __shared__ __align__(16) float Ks[CK * 36];
    __shared__ __align__(16) float Vs[CK * 36];
    __shared__ __align__(16) float Qs[TQ * 36];
    __shared__ float Ps[8][CK];

    for (int i = tid; i < TQ * D; i += 256) {
        int ql = i >> 5, d = i & 31;
        int qg = qt * TQ + ql;
        if (qg >= NQ) qg = NQ - 1;
        Qs[ql * 36 + d] = Q[(size_t)(b * NQ + qg) * E + h * D + d];
    }
    __syncthreads();

    const int* mrow[4];
    int qg_[4];
#pragma unroll
    for (int sub = 0; sub < 4; sub++) {
        int qg = qt * TQ + w * 4 + sub;
        qg_[sub] = qg;
        int qc = (qg < NQ) ? qg : NQ - 1;
        mrow[sub] = mask + (size_t)(b * NQ + qc) * NK;
    }

    float mv[4] = {-INFINITY, -INFINITY, -INFINITY, -INFINITY};
    float sv[4] = {0.f, 0.f, 0.f, 0.f};
    float av[4] = {0.f, 0.f, 0.f, 0.f};

    for (int k0 = 0; k0 < NK; k0 += CK) {
        for (int i = tid; i < CK * 8; i += 256) {
            int j = i >> 3, d4 = i & 7;
            size_t base = (size_t)(b * NK + k0 + j) * E + h * D + d4 * 4;
            *(float4*)&Ks[j * 36 + d4 * 4] = *(const float4*)&Kb[base];
            *(float4*)&Vs[j * 36 + d4 * 4] = *(const float4*)&Vb[base];
        }
        __syncthreads();

#pragma unroll
        for (int sub = 0; sub < 4; sub++) {
            const int ql = w * 4 + sub;
            float sc[4];
#pragma unroll
            for (int c = 0; c < 4; c++) {
                int key = c * 32 + lane;
                int mk = mrow[sub][k0 + key];
                float s;
                if (mk) {
                    s = 0.f;
#pragma unroll
                    for (int d4 = 0; d4 < 8; d4++) {
                        float4 kk = *(const float4*)&Ks[key * 36 + d4 * 4];
                        float4 qq = *(const float4*)&Qs[ql * 36 + d4 * 4];
                        s += kk.x * qq.x + kk.y * qq.y + kk.z * qq.z + kk.w * qq.w;
                    }
                    s *= ATTN_SCALE;
                } else {
                    s = -INFINITY;
                }
                sc[c] = s;
            }
            float cmax = fmaxf(fmaxf(sc[0], sc[1]), fmaxf(sc[2], sc[3]));
#pragma unroll
            for (int o = 16; o > 0; o >>= 1)
                cmax = fmaxf(cmax, __shfl_xor_sync(0xffffffff, cmax, o));

            float mOld = mv[sub];
            float mNew = fmaxf(mOld, cmax);
            float factor, psum = 0.f;
            if (mNew == -INFINITY) {
                factor = 1.f;
#pragma unroll
                for (int c = 0; c < 4; c++) Ps[w][c * 32 + lane] = 0.f;
            } else {
                factor = __expf(mOld - mNew);
#pragma unroll
                for (int c = 0; c < 4; c++) {
                    float p = (sc[c] == -INFINITY) ? 0.f : __expf(sc[c] - mNew);
                    psum += p;
                    Ps[w][c * 32 + lane] = p;
                }
            }
#pragma unroll
            for (int o = 16; o > 0; o >>= 1)
                psum += __shfl_xor_sync(0xffffffff, psum, o);
            __syncwarp();

            float a = av[sub] * factor;
#pragma unroll 4
            for (int j = 0; j < CK; j++)
                a += Ps[w][j] * Vs[j * 36 + lane];

            av[sub] = a;
            mv[sub] = mNew;
            sv[sub] = sv[sub] * factor + psum;
            __syncwarp();
        }
        __syncthreads();
    }

#pragma unroll
    for (int sub = 0; sub < 4; sub++) {
        if (qg_[sub] < NQ) {
            float inv = (sv[sub] > 0.f) ? 1.f / sv[sub] : 0.f;
            float o = av[sub] * inv;
            size_t idx = (size_t)(b * NQ + qg_[sub]) * E + h * D + lane;
            __nv_bfloat16 hh = __float2bfloat16_rn(o);
            ohi[idx] = hh;
            olo[idx] = __float2bfloat16_rn(o - __bfloat162float(hh));
        }
    }
}

// ================= LayerNorm (+residual, + optional split outs) =================
__global__ void ln_kernel(const float* __restrict__ x,
                          const float* __restrict__ res,
                          const float* __restrict__ gamma,
                          const float* __restrict__ beta,
                          float* __restrict__ out,
                          __nv_bfloat16* __restrict__ ohi,
                          __nv_bfloat16* __restrict__ olo) {
    const int row = blockIdx.x;
    const int tid = threadIdx.x;
    const int lane = tid & 31, wid = tid >> 5;
    __shared__ float r1[8], r2[8];

    size_t idx = (size_t)row * E + tid;
    float v = x[idx];
    if (res) v += res[idx];

    float s = v;
#pragma unroll
    for (int o = 16; o > 0; o >>= 1) s += __shfl_xor_sync(0xffffffff, s, o);
    if (lane == 0) r1[wid] = s;
    __syncthreads();
    float tot = 0.f;
#pragma unroll
    for (int i = 0; i < 8; i++) tot += r1[i];
    float mean = tot * (1.f / E);

    float d = v - mean;
    float s2 = d * d;
#pragma unroll
    for (int o = 16; o > 0; o >>= 1) s2 += __shfl_xor_sync(0xffffffff, s2, o);
    if (lane == 0) r2[wid] = s2;
    __syncthreads();
    float tv = 0.f;
#pragma unroll
    for (int i = 0; i < 8; i++) tv += r2[i];
    float o_ = d * rsqrtf(tv * (1.f / E) + 1e-5f) * gamma[tid] + beta[tid];
    out[idx] = o_;
    if (ohi) {
        __nv_bfloat16 h = __float2bfloat16_rn(o_);
        ohi[idx] = h;
        olo[idx] = __float2bfloat16_rn(o_ - __bfloat162float(h));
    }
}

// ================= host side =================
static inline void tc_gemm(const __nv_bfloat16* Ahi, const __nv_bfloat16* Alo,
                           const __nv_bfloat16* Whi, const __nv_bfloat16* Wlo,
                           const float* bias, float* C, int M, int N, int K) {
    dim3 grid(N / 128, (M + 127) / 128);
    tc_gemm_kernel<0, 0><<<grid, 128, SMG_TOTAL>>>(Ahi, Alo, Whi, Wlo, bias, C, nullptr, nullptr, M, N, K);
}
static inline void tc_gemm_relu_split(const __nv_bfloat16* Ahi, const __nv_bfloat16* Alo,
                                      const __nv_bfloat16* Whi, const __nv_bfloat16* Wlo,
                                      const float* bias, __nv_bfloat16* Chi, __nv_bfloat16* Clo,
                                      int M, int N, int K) {
    dim3 grid(N / 128, (M + 127) / 128);
    tc_gemm_kernel<1, 1><<<grid, 128, SMG_TOTAL>>>(Ahi, Alo, Whi, Wlo, bias, nullptr, Chi, Clo, M, N, K);
}

extern "C" void kernel_launch(void* const* d_in, const int* in_sizes, int n_in,
                              void* d_out, int out_size) {
    cudaFuncSetAttribute(tc_gemm_kernel<0, 0>, cudaFuncAttributeMaxDynamicSharedMemorySize, SMG_TOTAL);
    cudaFuncSetAttribute(tc_gemm_kernel<1, 1>, cudaFuncAttributeMaxDynamicSharedMemorySize, SMG_TOTAL);

    const float* tgt      = (const float*)d_in[0];
    const float* memory   = (const float*)d_in[1];
    const int*   gmask    = (const int*)d_in[2];
    const float* sa_wqkv  = (const float*)d_in[3];
    const float* sa_bqkv  = (const float*)d_in[4];
    const float* sa_wo    = (const float*)d_in[5];
    const float* sa_bo    = (const float*)d_in[6];
    const float* ca_wq    = (const float*)d_in[7];
    const float* ca_bq    = (const float*)d_in[8];
    const float* ca_wk    = (const float*)d_in[9];
    const float* ca_bk    = (const float*)d_in[10];
    const float* ca_wv    = (const float*)d_in[11];
    const float* ca_bv    = (const float*)d_in[12];
    const float* ca_wo    = (const float*)d_in[13];
    const float* ca_bo    = (const float*)d_in[14];
    const float* f_w1     = (const float*)d_in[15];
    const float* f_b1     = (const float*)d_in[16];
    const float* f_w2     = (const float*)d_in[17];
    const float* f_b2     = (const float*)d_in[18];
    const float* ln1g     = (const float*)d_in[19];
    const float* ln1b     = (const float*)d_in[20];
    const float* ln2g     = (const float*)d_in[21];
    const float* ln2b     = (const float*)d_in[22];
    const float* ln3g     = (const float*)d_in[23];
    const float* ln3b     = (const float*)d_in[24];
    const float* lnfg     = (const float*)d_in[25];
    const float* lnfb     = (const float*)d_in[26];

    float *t, *qkv, *proj, *qb, *kb, *vb;
    cudaGetSymbolAddress((void**)&t,    g_t);
    cudaGetSymbolAddress((void**)&qkv,  g_qkv);
    cudaGetSymbolAddress((void**)&proj, g_proj);
    cudaGetSymbolAddress((void**)&qb,   g_q);
    cudaGetSymbolAddress((void**)&kb,   g_k);
    cudaGetSymbolAddress((void**)&vb,   g_v);

    __nv_bfloat16 *whi, *wlo, *thi, *tlo, *ahi, *alo, *mhi, *mlo, *fhi, *flo;
    cudaGetSymbolAddress((void**)&whi, g_whi);
    cudaGetSymbolAddress((void**)&wlo, g_wlo);
    cudaGetSymbolAddress((void**)&thi, g_thi);
    cudaGetSymbolAddress((void**)&tlo, g_tlo);
    cudaGetSymbolAddress((void**)&ahi, g_ahi);
    cudaGetSymbolAddress((void**)&alo, g_alo);
    cudaGetSymbolAddress((void**)&mhi, g_mhi);
    cudaGetSymbolAddress((void**)&mlo, g_mlo);
    cudaGetSymbolAddress((void**)&fhi, g_fhi);
    cudaGetSymbolAddress((void**)&flo, g_flo);

    // ---- one mega split launch: 8 weight groups + memory + tgt(copy) ----
    {
        SplitArgs a;
        const float* srcs[10] = {sa_wqkv, sa_wo, ca_wq, ca_wk, ca_wv, ca_wo, f_w1, f_w2, memory, tgt};
        long long sizes[10] = {
            (long long)LAYERS * 3 * E * E, (long long)LAYERS * E * E, (long long)LAYERS * E * E,
            (long long)LAYERS * E * E, (long long)LAYERS * E * E, (long long)LAYERS * E * E,
            (long long)LAYERS * FF * E, (long long)LAYERS * E * FF,
            (long long)MK_ROWS * E, (long long)MQ_ROWS * E};
        long long offs[8] = {OFF_WQKV, OFF_WO, OFF_WQ, OFF_WK, OFF_WV, OFF_WCO, OFF_W1, OFF_W2};
        a.cum[0] = 0;
        for (int s = 0; s < 10; s++) {
            a.src[s] = srcs[s];
            a.cpy[s] = nullptr;
            a.cum[s + 1] = a.cum[s] + sizes[s];
            if (s < 8)      { a.hi[s] = whi + offs[s]; a.lo[s] = wlo + offs[s]; }
            else if (s == 8){ a.hi[s] = mhi;           a.lo[s] = mlo; }
            else            { a.hi[s] = thi;           a.lo[s] = tlo; a.cpy[s] = t; }
        }
        long long total = a.cum[10];
        mega_split_kernel<<<(unsigned)((total + 255) / 256), 256>>>(a);
    }

    dim3 sa_grid(NQ, H, B);
    dim3 ca_grid((NQ + TQ - 1) / TQ, H, B);

    for (int l = 0; l < LAYERS; l++) {
        const size_t wEE = (size_t)l * E * E;
        const __nv_bfloat16* wqkv_h = whi + OFF_WQKV + (size_t)l * 3 * E * E;
        const __nv_bfloat16* wqkv_l = wlo + OFF_WQKV + (size_t)l * 3 * E * E;
        const float* bqkv = sa_bqkv + (size_t)l * 3 * E;
        const float* bo   = sa_bo + (size_t)l * E;
        const float* bq   = ca_bq + (size_t)l * E;
        const float* bk   = ca_bk + (size_t)l * E;
        const float* bv   = ca_bv + (size_t)l * E;
        const float* bco  = ca_bo + (size_t)l * E;
        const float* b1   = f_b1 + (size_t)l * FF;
        const float* b2   = f_b2 + (size_t)l * E;
        const float* g1   = ln1g + (size_t)l * E;
        const float* be1  = ln1b + (size_t)l * E;
        const float* g2   = ln2g + (size_t)l * E;
        const float* be2  = ln2b + (size_t)l * E;
        const float* g3   = ln3g + (size_t)l * E;
        const float* be3  = ln3b + (size_t)l * E;

        // --- self-attention ---
        tc_gemm(thi, tlo, wqkv_h, wqkv_l, bqkv, qkv, MQ_ROWS, 3 * E, E);
        sa_attn_kernel<<<sa_grid, 128>>>(qkv, ahi, alo);
        tc_gemm(ahi, alo, whi + OFF_WO + wEE, wlo + OFF_WO + wEE, bo, proj, MQ_ROWS, E, E);
        ln_kernel<<<MQ_ROWS, E>>>(t, proj, g1, be1, t, thi, tlo);

        // --- cross-attention ---
        tc_gemm(mhi, mlo, whi + OFF_WK + wEE, wlo + OFF_WK + wEE, bk, kb, MK_ROWS, E, E);
        tc_gemm(mhi, mlo, whi + OFF_WV + wEE, wlo + OFF_WV + wEE, bv, vb, MK_ROWS, E, E);
        tc_gemm(thi, tlo, whi + OFF_WQ + wEE, wlo + OFF_WQ + wEE, bq, qb, MQ_ROWS, E, E);
        ca_flash_kernel<<<ca_grid, 256>>>(qb, kb, vb, gmask, ahi, alo);
        tc_gemm(ahi, alo, whi + OFF_WCO + wEE, wlo + OFF_WCO + wEE, bco, proj, MQ_ROWS, E, E);
        ln_kernel<<<MQ_ROWS, E>>>(t, proj, g2, be2, t, thi, tlo);

        // --- FFN ---
        tc_gemm_relu_split(thi, tlo, whi + OFF_W1 + (size_t)l * FF * E, wlo + OFF_W1 + (size_t)l * FF * E,
                           b1, fhi, flo, MQ_ROWS, FF, E);
        tc_gemm(fhi, flo, whi + OFF_W2 + (size_t)l * E * FF, wlo + OFF_W2 + (size_t)l * E * FF,
                b2, proj, MQ_ROWS, E, FF);
        ln_kernel<<<MQ_ROWS, E>>>(t, proj, g3, be3, t, thi, tlo);
    }

    ln_kernel<<<MQ_ROWS, E>>>(t, nullptr, lnfg, lnfb, (float*)d_out, nullptr, nullptr);
}

// round 8
// speedup vs baseline: 1.5957x; 1.5957x over previous
#include <cuda_runtime.h>
#include <cuda_bf16.h>
#include <math.h>
#include <stdint.h>

// Problem constants
#define B   8
#define NQ  300
#define NK  4096
#define E   256
#define H   8
#define D   32
#define FF  2048
#define LAYERS 6
#define ATTN_SCALE 0.17677669529663687f

#define TQ 32      // attention query tile
#define CK 128     // attention key chunk

#define MQ_ROWS (B * NQ)   // 2400
#define MK_ROWS (B * NK)   // 32768

#if defined(__CUDA_ARCH_SPECIFIC__) || defined(__CUDA_ARCH_FEAT_SM103_ALL) || defined(__CUDA_ARCH_FEAT_SM100_ALL)
#define HAS_TC 1
#else
#define HAS_TC 0
#endif

// ---------------- fp32 scratch ----------------
__device__ float g_t[MQ_ROWS * E];
__device__ float g_qkv[MQ_ROWS * 3 * E];
__device__ float g_proj[MQ_ROWS * E];
__device__ float g_q[MQ_ROWS * E];
__device__ float g_k[MK_ROWS * E];
__device__ float g_v[MK_ROWS * E];

// ---------------- bf16 hi/lo scratch ----------------
#define OFF_WQKV 0
#define OFF_WO   1179648
#define OFF_WQ   1572864
#define OFF_WK   1966080
#define OFF_WV   2359296
#define OFF_WCO  2752512
#define OFF_W1   3145728
#define OFF_W2   6291456
#define W_TOTAL  9437184

__device__ __nv_bfloat16 g_whi[W_TOTAL];
__device__ __nv_bfloat16 g_wlo[W_TOTAL];
__device__ __nv_bfloat16 g_thi[MQ_ROWS * E],  g_tlo[MQ_ROWS * E];
__device__ __nv_bfloat16 g_ahi[MQ_ROWS * E],  g_alo[MQ_ROWS * E];
__device__ __nv_bfloat16 g_mhi[MK_ROWS * E],  g_mlo[MK_ROWS * E];
__device__ __nv_bfloat16 g_fhi[MQ_ROWS * FF], g_flo[MQ_ROWS * FF];

// ================= PTX helpers =================
__device__ __forceinline__ uint32_t smem_u32(const void* p) {
    uint32_t a;
    asm("{ .reg .u64 t; cvta.to.shared.u64 t, %1; cvt.u32.u64 %0, t; }" : "=r"(a) : "l"(p));
    return a;
}

// packed fp32x2 FMA (sm_100+; gated like tcgen05 so generic PTX pass compiles)
__device__ __forceinline__ float2 ffma2(float2 a, float2 b, float2 c) {
#if HAS_TC
    float2 d;
    asm("{\n\t"
        ".reg .b64 ra, rb, rc, rd;\n\t"
        "mov.b64 ra, {%2, %3};\n\t"
        "mov.b64 rb, {%4, %5};\n\t"
        "mov.b64 rc, {%6, %7};\n\t"
        "fma.rn.f32x2 rd, ra, rb, rc;\n\t"
        "mov.b64 {%0, %1}, rd;\n\t"
        "}" : "=f"(d.x), "=f"(d.y)
            : "f"(a.x), "f"(a.y), "f"(b.x), "f"(b.y), "f"(c.x), "f"(c.y));
    return d;
#else
    return make_float2(fmaf(a.x, b.x, c.x), fmaf(a.y, b.y, c.y));
#endif
}

#if HAS_TC
__device__ __forceinline__ uint32_t elect_one() {
    uint32_t pred;
    asm volatile("{.reg .pred p; elect.sync _|p, 0xFFFFFFFF; selp.b32 %0, 1, 0, p;}" : "=r"(pred));
    return pred;
}
#define TC_ALLOC(sm, n)  asm volatile("tcgen05.alloc.cta_group::1.sync.aligned.shared::cta.b32 [%0], %1;" :: "r"((uint32_t)(sm)), "r"((uint32_t)(n)) : "memory")
#define TC_DEALLOC(t, n) asm volatile("tcgen05.dealloc.cta_group::1.sync.aligned.b32 %0, %1;" :: "r"(t), "r"((uint32_t)(n)))
#define TC_RELINQ()      asm volatile("tcgen05.relinquish_alloc_permit.cta_group::1.sync.aligned;")
#define TC_COMMIT(mb)    asm volatile("tcgen05.commit.cta_group::1.mbarrier::arrive::one.shared::cluster.b64 [%0];" :: "r"((uint32_t)(mb)) : "memory")
#define TC_WAIT_LD()     asm volatile("tcgen05.wait::ld.sync.aligned;" ::: "memory")
#define TC_FENCE_AFTER() asm volatile("tcgen05.fence::after_thread_sync;" ::: "memory")
#define FENCE_ASYNC()    asm volatile("fence.proxy.async.shared::cta;" ::: "memory")
#define MBAR_INIT(mb, c) asm volatile("mbarrier.init.shared.b64 [%0], %1;" :: "r"((uint32_t)(mb)), "r"((uint32_t)(c)) : "memory")

#define MBAR_WAIT(mb, ph) do { \
    uint32_t _m = (uint32_t)(mb), _p = (uint32_t)(ph), _d; \
    asm volatile("{.reg .pred p; mbarrier.try_wait.parity.acquire.cta.shared::cta.b64 p, [%1], %2; selp.b32 %0, 1, 0, p;}" \
        : "=r"(_d) : "r"(_m), "r"(_p) : "memory"); \
    if (!_d) { \
        asm volatile("{.reg .pred P1; WL_%=: mbarrier.try_wait.parity.acquire.cta.shared::cta.b64 P1, [%0], %1, 0x989680;" \
            "@P1 bra.uni WD_%=; bra.uni WL_%=; WD_%=: }" :: "r"(_m), "r"(_p) : "memory"); \
    } \
} while (0)

#define TC_LD_X32(r, addr) \
    asm volatile("tcgen05.ld.sync.aligned.32x32b.x32.b32 " \
        "{%0,%1,%2,%3,%4,%5,%6,%7,%8,%9,%10,%11,%12,%13,%14,%15," \
        "%16,%17,%18,%19,%20,%21,%22,%23,%24,%25,%26,%27,%28,%29,%30,%31}, [%32];" \
        : "=r"((r)[0]),"=r"((r)[1]),"=r"((r)[2]),"=r"((r)[3]),"=r"((r)[4]),"=r"((r)[5]),"=r"((r)[6]),"=r"((r)[7]), \
          "=r"((r)[8]),"=r"((r)[9]),"=r"((r)[10]),"=r"((r)[11]),"=r"((r)[12]),"=r"((r)[13]),"=r"((r)[14]),"=r"((r)[15]), \
          "=r"((r)[16]),"=r"((r)[17]),"=r"((r)[18]),"=r"((r)[19]),"=r"((r)[20]),"=r"((r)[21]),"=r"((r)[22]),"=r"((r)[23]), \
          "=r"((r)[24]),"=r"((r)[25]),"=r"((r)[26]),"=r"((r)[27]),"=r"((r)[28]),"=r"((r)[29]),"=r"((r)[30]),"=r"((r)[31]) \
        : "r"(addr))

__device__ __forceinline__ void mma_f16_ss(uint32_t d, uint64_t a, uint64_t b,
                                           uint32_t idesc, bool acc) {
    uint32_t e = acc ? 1u : 0u;
    asm volatile(
        "{\n\t.reg .pred p;\n\tsetp.ne.u32 p, %4, 0;\n\t"
        "tcgen05.mma.cta_group::1.kind::f16 [%0], %1, %2, %3, {%5, %5, %5, %5}, p;\n\t}"
        :: "r"(d), "l"(a), "l"(b), "r"(idesc), "r"(e), "r"(0u) : "memory");
}
#endif // HAS_TC

#define SW128(x) ((x) ^ (((x) >> 3) & 0x70))
static constexpr uint64_t DESC_BASE_SW128 =
    (uint64_t(2) << 61) | (uint64_t(1) << 46) | (uint64_t(64) << 32) | (uint64_t(1) << 16);
#define MK_DESC(a) (DESC_BASE_SW128 | ((uint64_t)((a) >> 4) & 0x3FFF))

// idesc: F32 accum, bf16 A/B, M=128, N=128
#define TC_IDESC ((1u << 4) | (1u << 7) | (1u << 10) | (16u << 17) | (8u << 24))

// ================= tcgen05 split-bf16 GEMM (double-buffered) =================
#define SMG_MBAR   0
#define SMG_TMEMP  16
#define SMG_BIAS   512
#define SMG_BUF0   1024
#define SMG_BUFSZ  65536
#define SMG_TOTAL  (1024 + 2 * 65536 + 1024)

template <int RELU, int SPLIT>
__global__ void __launch_bounds__(128, 1) __cluster_dims__(1, 1, 1)
tc_gemm_kernel(const __nv_bfloat16* __restrict__ Ahi, const __nv_bfloat16* __restrict__ Alo,
               const __nv_bfloat16* __restrict__ Whi, const __nv_bfloat16* __restrict__ Wlo,
               const float* __restrict__ bias,
               float* __restrict__ C,
               __nv_bfloat16* __restrict__ Chi, __nv_bfloat16* __restrict__ Clo,
               int M, int N, int K) {
    extern __shared__ __align__(16) char smem_raw[];
    char* smem = (char*)((((uintptr_t)smem_raw) + 1023) & ~(uintptr_t)1023);
    const uint32_t sb = smem_u32(smem);
    const int tid = threadIdx.x;
    const int wid = tid >> 5, lane = tid & 31;
    const int n0 = blockIdx.x * 128;
    const int m0 = blockIdx.y * 128;
    (void)sb; (void)wid; (void)lane;

#if HAS_TC
    if (wid == 0) {
        TC_ALLOC(sb + SMG_TMEMP, 128);
        TC_RELINQ();
    }
    if (tid == 0) { MBAR_INIT(sb + SMG_MBAR, 1); }
    if (tid < 128) ((float*)(smem + SMG_BIAS))[tid] = bias[n0 + tid];

    const int nchunks = K >> 6;

#define STAGE_CHUNK(bsel, kc) do { \
    const int kel = (kc) * 64; \
    const uint32_t bbase = SMG_BUF0 + (bsel) * SMG_BUFSZ; \
    _Pragma("unroll") \
    for (int it = 0; it < 32; it++) { \
        int idx = it * 128 + tid; \
        int tile = idx >> 10; \
        int r = (idx >> 3) & 127; \
        int c16 = idx & 7; \
        uint4 val = make_uint4(0, 0, 0, 0); \
        if (tile < 2) { \
            int m = m0 + r; \
            if (m < M) { \
                const __nv_bfloat16* src = (tile == 0) ? Ahi : Alo; \
                val = *(const uint4*)&src[(size_t)m * K + kel + c16 * 8]; \
            } \
        } else { \
            int n = n0 + r; \
            const __nv_bfloat16* src = (tile == 2) ? Whi : Wlo; \
            val = *(const uint4*)&src[(size_t)n * K + kel + c16 * 8]; \
        } \
        uint32_t off = bbase + tile * 16384 + SW128((uint32_t)(r * 128 + c16 * 16)); \
        *(uint4*)(smem + off) = val; \
    } \
} while (0)

    STAGE_CHUNK(0, 0);
    __syncthreads();

    uint32_t tmem;
    asm volatile("ld.shared.b32 %0, [%1];" : "=r"(tmem) : "r"(sb + SMG_TMEMP));

    int phase = 0;
    for (int kc = 0; kc < nchunks; kc++) {
        const int bsel = kc & 1;
        const uint32_t bbase = sb + SMG_BUF0 + bsel * SMG_BUFSZ;
        if (wid == 0) {
            if (elect_one()) {
                FENCE_ASYNC();
                const uint64_t dAhi = MK_DESC(bbase);
                const uint64_t dAlo = MK_DESC(bbase + 16384);
                const uint64_t dBhi = MK_DESC(bbase + 32768);
                const uint64_t dBlo = MK_DESC(bbase + 49152);
                bool first = (kc == 0);
#pragma unroll
                for (int ks = 0; ks < 4; ks++)
                    mma_f16_ss(tmem, dAhi + ks * 2, dBhi + ks * 2, TC_IDESC, !(first && ks == 0));
#pragma unroll
                for (int ks = 0; ks < 4; ks++)
                    mma_f16_ss(tmem, dAhi + ks * 2, dBlo + ks * 2, TC_IDESC, true);
#pragma unroll
                for (int ks = 0; ks < 4; ks++)
                    mma_f16_ss(tmem, dAlo + ks * 2, dBhi + ks * 2, TC_IDESC, true);
                TC_COMMIT(sb + SMG_MBAR);
            }
        }
        if (kc + 1 < nchunks) {
            STAGE_CHUNK((kc + 1) & 1, kc + 1);
        }
        MBAR_WAIT(sb + SMG_MBAR, phase);
        phase ^= 1;
        __syncthreads();
    }
#undef STAGE_CHUNK

    TC_FENCE_AFTER();

    const float* bsm = (const float*)(smem + SMG_BIAS);
    const int m = m0 + wid * 32 + lane;
#pragma unroll
    for (int cc = 0; cc < 4; cc++) {
        uint32_t dr[32];
        TC_LD_X32(dr, tmem + cc * 32);
        TC_WAIT_LD();
        if (m < M) {
            const int nb = n0 + cc * 32;
            if (SPLIT) {
#pragma unroll
                for (int j2 = 0; j2 < 16; j2++) {
                    float v0 = __uint_as_float(dr[j2 * 2 + 0]) + bsm[cc * 32 + j2 * 2 + 0];
                    float v1 = __uint_as_float(dr[j2 * 2 + 1]) + bsm[cc * 32 + j2 * 2 + 1];
                    if (RELU) { v0 = fmaxf(v0, 0.f); v1 = fmaxf(v1, 0.f); }
                    __nv_bfloat16 h0 = __float2bfloat16_rn(v0);
                    __nv_bfloat16 h1 = __float2bfloat16_rn(v1);
                    __nv_bfloat16 l0 = __float2bfloat16_rn(v0 - __bfloat162float(h0));
                    __nv_bfloat16 l1 = __float2bfloat16_rn(v1 - __bfloat162float(h1));
                    *(__nv_bfloat162*)&Chi[(size_t)m * N + nb + j2 * 2] = __nv_bfloat162(h0, h1);
                    *(__nv_bfloat162*)&Clo[(size_t)m * N + nb + j2 * 2] = __nv_bfloat162(l0, l1);
                }
            } else {
                float* crow = &C[(size_t)m * N + nb];
#pragma unroll
                for (int c4 = 0; c4 < 8; c4++) {
                    float4 o;
                    o.x = __uint_as_float(dr[c4 * 4 + 0]) + bsm[cc * 32 + c4 * 4 + 0];
                    o.y = __uint_as_float(dr[c4 * 4 + 1]) + bsm[cc * 32 + c4 * 4 + 1];
                    o.z = __uint_as_float(dr[c4 * 4 + 2]) + bsm[cc * 32 + c4 * 4 + 2];
                    o.w = __uint_as_float(dr[c4 * 4 + 3]) + bsm[cc * 32 + c4 * 4 + 3];
                    if (RELU) {
                        o.x = fmaxf(o.x, 0.f); o.y = fmaxf(o.y, 0.f);
                        o.z = fmaxf(o.z, 0.f); o.w = fmaxf(o.w, 0.f);
                    }
                    *(float4*)&crow[c4 * 4] = o;
                }
            }
        }
    }

    __syncthreads();
    if (wid == 0) { TC_DEALLOC(tmem, 128); }
#else
    // generic-PTX fallback (insurance; never the loaded image on sm_103a)
    const int m = m0 + tid;
    if (m < M) {
        for (int cg = 0; cg < 4; cg++) {
            float acc[32];
#pragma unroll
            for (int j = 0; j < 32; j++) acc[j] = bias[n0 + cg * 32 + j];
            for (int k = 0; k < K; k++) {
                float a = __bfloat162float(Ahi[(size_t)m * K + k]) +
                          __bfloat162float(Alo[(size_t)m * K + k]);
#pragma unroll
                for (int j = 0; j < 32; j++) {
                    int n = n0 + cg * 32 + j;
                    float w = __bfloat162float(Whi[(size_t)n * K + k]) +
                              __bfloat162float(Wlo[(size_t)n * K + k]);
                    acc[j] += a * w;
                }
            }
#pragma unroll
            for (int j = 0; j < 32; j++) {
                float v = acc[j];
                if (RELU) v = fmaxf(v, 0.f);
                int n = n0 + cg * 32 + j;
                if (SPLIT) {
                    __nv_bfloat16 h = __float2bfloat16_rn(v);
                    Chi[(size_t)m * N + n] = h;
                    Clo[(size_t)m * N + n] = __float2bfloat16_rn(v - __bfloat162float(h));
                } else {
                    C[(size_t)m * N + n] = v;
                }
            }
        }
    }
#endif
}

// ================= mega split =================
struct SplitArgs {
    const float* src[10];
    __nv_bfloat16* hi[10];
    __nv_bfloat16* lo[10];
    float* cpy[10];
    long long cum[11];
};

__global__ void mega_split_kernel(SplitArgs a) {
    long long i = (long long)blockIdx.x * blockDim.x + threadIdx.x;
    if (i >= a.cum[10]) return;
    int s = 0;
#pragma unroll
    for (int k = 0; k < 10; k++)
        if (i >= a.cum[k + 1]) s = k + 1;
    long long off = i - a.cum[s];
    float v = a.src[s][off];
    __nv_bfloat16 h = __float2bfloat16_rn(v);
    a.hi[s][off] = h;
    a.lo[s][off] = __float2bfloat16_rn(v - __bfloat162float(h));
    if (a.cpy[s]) a.cpy[s][off] = v;
}

// ================= unified tiled flash attention (SA + CA) =================
// Grid: (ceil(nq/TQ), H, B), 256 threads = 8 warps, 4 queries/warp.
// Q rows: Qp + ((b*nq+q)*qstride + h*D); K/V rows: Kp/Vp + ((b*nk+j)*kvstride + h*D).
// mask may be null (SA). Output split bf16 at stride E.
__global__ void __launch_bounds__(256)
flash_attn_kernel(const float* __restrict__ Qp, int qstride,
                  const float* __restrict__ Kp, const float* __restrict__ Vp, int kvstride,
                  int nq, int nk,
                  const int* __restrict__ mask,
                  __nv_bfloat16* __restrict__ ohi, __nv_bfloat16* __restrict__ olo) {
    const int qt = blockIdx.x, h = blockIdx.y, b = blockIdx.z;
    const int tid = threadIdx.x;
    const int w = tid >> 5, lane = tid & 31;

    __shared__ __align__(16) float Ks[CK * 36];
    __shared__ __align__(16) float Vs[CK * 36];
    __shared__ __align__(16) float Qs[TQ * 36];
    __shared__ __align__(16) float Psm[8][4][CK];

    // load Q tile (clamped rows)
    for (int i = tid; i < TQ * 8; i += 256) {
        int ql = i >> 3, d4 = i & 7;
        int qg = qt * TQ + ql;
        if (qg >= nq) qg = nq - 1;
        *(float4*)&Qs[ql * 36 + d4 * 4] =
            *(const float4*)&Qp[((size_t)(b * nq + qg)) * qstride + h * D + d4 * 4];
    }
    __syncthreads();

    int qg_[4];
    const int* mrow[4];
#pragma unroll
    for (int sub = 0; sub < 4; sub++) {
        int qg = qt * TQ + w * 4 + sub;
        qg_[sub] = qg;
        int qc = (qg < nq) ? qg : nq - 1;
        mrow[sub] = mask ? (mask + ((size_t)(b * nq + qc)) * nk) : nullptr;
    }

    float mv[4] = {-INFINITY, -INFINITY, -INFINITY, -INFINITY};
    float sv[4] = {0.f, 0.f, 0.f, 0.f};
    float2 av2[4] = {{0.f, 0.f}, {0.f, 0.f}, {0.f, 0.f}, {0.f, 0.f}};

    for (int k0 = 0; k0 < nk; k0 += CK) {
        // stage K,V (zero-pad past nk)
        for (int i = tid; i < CK * 8; i += 256) {
            int j = i >> 3, d4 = i & 7;
            int kg = k0 + j;
            float4 kv = make_float4(0.f, 0.f, 0.f, 0.f);
            float4 vv = make_float4(0.f, 0.f, 0.f, 0.f);
            if (kg < nk) {
                size_t base = ((size_t)(b * nk + kg)) * kvstride + h * D + d4 * 4;
                kv = *(const float4*)&Kp[base];
                vv = *(const float4*)&Vp[base];
            }
            *(float4*)&Ks[j * 36 + d4 * 4] = kv;
            *(float4*)&Vs[j * 36 + d4 * 4] = vv;
        }
        __syncthreads();

        // ---- score phase: hoist K row across the warp's 4 queries ----
        float sc[4][4];
#pragma unroll
        for (int c = 0; c < 4; c++) {
            const int key = c * 32 + lane;
            const bool kval = (k0 + key < nk);
            float4 k4[8];
#pragma unroll
            for (int d4 = 0; d4 < 8; d4++)
                k4[d4] = *(const float4*)&Ks[key * 36 + d4 * 4];
#pragma unroll
            for (int sub = 0; sub < 4; sub++) {
                const int ql = w * 4 + sub;
                float2 s2 = make_float2(0.f, 0.f);
#pragma unroll
                for (int d4 = 0; d4 < 8; d4++) {
                    float4 q4 = *(const float4*)&Qs[ql * 36 + d4 * 4];
                    s2 = ffma2(make_float2(k4[d4].x, k4[d4].y), make_float2(q4.x, q4.y), s2);
                    s2 = ffma2(make_float2(k4[d4].z, k4[d4].w), make_float2(q4.z, q4.w), s2);
                }
                float s = s2.x + s2.y;
                bool val = kval && (!mask || (mrow[sub][k0 + key] != 0));
                sc[sub][c] = val ? (s * ATTN_SCALE) : -INFINITY;
            }
        }

        // ---- online softmax per sub ----
#pragma unroll
        for (int sub = 0; sub < 4; sub++) {
            float cmax = fmaxf(fmaxf(sc[sub][0], sc[sub][1]), fmaxf(sc[sub][2], sc[sub][3]));
#pragma unroll
            for (int o = 16; o > 0; o >>= 1)
                cmax = fmaxf(cmax, __shfl_xor_sync(0xffffffff, cmax, o));
            float mOld = mv[sub];
            float mNew = fmaxf(mOld, cmax);
            float factor, psum = 0.f;
            if (mNew == -INFINITY) {
                factor = 1.f;
#pragma unroll
                for (int c = 0; c < 4; c++) Psm[w][sub][c * 32 + lane] = 0.f;
            } else {
                factor = __expf(mOld - mNew);
#pragma unroll
                for (int c = 0; c < 4; c++) {
                    float p = (sc[sub][c] == -INFINITY) ? 0.f : __expf(sc[sub][c] - mNew);
                    psum += p;
                    Psm[w][sub][c * 32 + lane] = p;
                }
            }
#pragma unroll
            for (int o = 16; o > 0; o >>= 1)
                psum += __shfl_xor_sync(0xffffffff, psum, o);
            sv[sub] = sv[sub] * factor + psum;
            mv[sub] = mNew;
            av2[sub].x *= factor;
            av2[sub].y *= factor;
        }
        __syncwarp();

        // ---- V phase: one V sweep, 4 accumulators ----
#pragma unroll 4
        for (int j4 = 0; j4 < 32; j4++) {
            float v0 = Vs[(j4 * 4 + 0) * 36 + lane];
            float v1 = Vs[(j4 * 4 + 1) * 36 + lane];
            float v2 = Vs[(j4 * 4 + 2) * 36 + lane];
            float v3 = Vs[(j4 * 4 + 3) * 36 + lane];
#pragma unroll
            for (int sub = 0; sub < 4; sub++) {
                float4 p = *(const float4*)&Psm[w][sub][j4 * 4];
                av2[sub] = ffma2(make_float2(p.x, p.y), make_float2(v0, v1), av2[sub]);
                av2[sub] = ffma2(make_float2(p.z, p.w), make_float2(v2, v3), av2[sub]);
            }
        }
        __syncthreads();
    }

#pragma unroll
    for (int sub = 0; sub < 4; sub++) {
        if (qg_[sub] < nq) {
            float a = av2[sub].x + av2[sub].y;
            float inv = (sv[sub] > 0.f) ? 1.f / sv[sub] : 0.f;
            float o = a * inv;
            size_t idx = (size_t)(b * nq + qg_[sub]) * E + h * D + lane;
            __nv_bfloat16 hh = __float2bfloat16_rn(o);
            ohi[idx] = hh;
            olo[idx] = __float2bfloat16_rn(o - __bfloat162float(hh));
        }
    }
}

// ================= LayerNorm (+residual, + optional split outs) =================
__global__ void ln_kernel(const float* __restrict__ x,
                          const float* __restrict__ res,
                          const float* __restrict__ gamma,
                          const float* __restrict__ beta,
                          float* __restrict__ out,
                          __nv_bfloat16* __restrict__ ohi,
                          __nv_bfloat16* __restrict__ olo) {
    const int row = blockIdx.x;
    const int tid = threadIdx.x;
    const int lane = tid & 31, wid = tid >> 5;
    __shared__ float r1[8], r2[8];

    size_t idx = (size_t)row * E + tid;
    float v = x[idx];
    if (res) v += res[idx];

    float s = v;
#pragma unroll
    for (int o = 16; o > 0; o >>= 1) s += __shfl_xor_sync(0xffffffff, s, o);
    if (lane == 0) r1[wid] = s;
    __syncthreads();
    float tot = 0.f;
#pragma unroll
    for (int i = 0; i < 8; i++) tot += r1[i];
    float mean = tot * (1.f / E);

    float d = v - mean;
    float s2 = d * d;
#pragma unroll
    for (int o = 16; o > 0; o >>= 1) s2 += __shfl_xor_sync(0xffffffff, s2, o);
    if (lane == 0) r2[wid] = s2;
    __syncthreads();
    float tv = 0.f;
#pragma unroll
    for (int i = 0; i < 8; i++) tv += r2[i];
    float o_ = d * rsqrtf(tv * (1.f / E) + 1e-5f) * gamma[tid] + beta[tid];
    out[idx] = o_;
    if (ohi) {
        __nv_bfloat16 h = __float2bfloat16_rn(o_);
        ohi[idx] = h;
        olo[idx] = __float2bfloat16_rn(o_ - __bfloat162float(h));
    }
}

// ================= host side =================
static inline void tc_gemm(const __nv_bfloat16* Ahi, const __nv_bfloat16* Alo,
                           const __nv_bfloat16* Whi, const __nv_bfloat16* Wlo,
                           const float* bias, float* C, int M, int N, int K) {
    dim3 grid(N / 128, (M + 127) / 128);
    tc_gemm_kernel<0, 0><<<grid, 128, SMG_TOTAL>>>(Ahi, Alo, Whi, Wlo, bias, C, nullptr, nullptr, M, N, K);
}
static inline void tc_gemm_relu_split(const __nv_bfloat16* Ahi, const __nv_bfloat16* Alo,
                                      const __nv_bfloat16* Whi, const __nv_bfloat16* Wlo,
                                      const float* bias, __nv_bfloat16* Chi, __nv_bfloat16* Clo,
                                      int M, int N, int K) {
    dim3 grid(N / 128, (M + 127) / 128);
    tc_gemm_kernel<1, 1><<<grid, 128, SMG_TOTAL>>>(Ahi, Alo, Whi, Wlo, bias, nullptr, Chi, Clo, M, N, K);
}

extern "C" void kernel_launch(void* const* d_in, const int* in_sizes, int n_in,
                              void* d_out, int out_size) {
    cudaFuncSetAttribute(tc_gemm_kernel<0, 0>, cudaFuncAttributeMaxDynamicSharedMemorySize, SMG_TOTAL);
    cudaFuncSetAttribute(tc_gemm_kernel<1, 1>, cudaFuncAttributeMaxDynamicSharedMemorySize, SMG_TOTAL);

    const float* tgt      = (const float*)d_in[0];
    const float* memory   = (const float*)d_in[1];
    const int*   gmask    = (const int*)d_in[2];
    const float* sa_wqkv  = (const float*)d_in[3];
    const float* sa_bqkv  = (const float*)d_in[4];
    const float* sa_wo    = (const float*)d_in[5];
    const float* sa_bo    = (const float*)d_in[6];
    const float* ca_wq    = (const float*)d_in[7];
    const float* ca_bq    = (const float*)d_in[8];
    const float* ca_wk    = (const float*)d_in[9];
    const float* ca_bk    = (const float*)d_in[10];
    const float* ca_wv    = (const float*)d_in[11];
    const float* ca_bv    = (const float*)d_in[12];
    const float* ca_wo    = (const float*)d_in[13];
    const float* ca_bo    = (const float*)d_in[14];
    const float* f_w1     = (const float*)d_in[15];
    const float* f_b1     = (const float*)d_in[16];
    const float* f_w2     = (const float*)d_in[17];
    const float* f_b2     = (const float*)d_in[18];
    const float* ln1g     = (const float*)d_in[19];
    const float* ln1b     = (const float*)d_in[20];
    const float* ln2g     = (const float*)d_in[21];
    const float* ln2b     = (const float*)d_in[22];
    const float* ln3g     = (const float*)d_in[23];
    const float* ln3b     = (const float*)d_in[24];
    const float* lnfg     = (const float*)d_in[25];
    const float* lnfb     = (const float*)d_in[26];

    float *t, *qkv, *proj, *qb, *kb, *vb;
    cudaGetSymbolAddress((void**)&t,    g_t);
    cudaGetSymbolAddress((void**)&qkv,  g_qkv);
    cudaGetSymbolAddress((void**)&proj, g_proj);
    cudaGetSymbolAddress((void**)&qb,   g_q);
    cudaGetSymbolAddress((void**)&kb,   g_k);
    cudaGetSymbolAddress((void**)&vb,   g_v);

    __nv_bfloat16 *whi, *wlo, *thi, *tlo, *ahi, *alo, *mhi, *mlo, *fhi, *flo;
    cudaGetSymbolAddress((void**)&whi, g_whi);
    cudaGetSymbolAddress((void**)&wlo, g_wlo);
    cudaGetSymbolAddress((void**)&thi, g_thi);
    cudaGetSymbolAddress((void**)&tlo, g_tlo);
    cudaGetSymbolAddress((void**)&ahi, g_ahi);
    cudaGetSymbolAddress((void**)&alo, g_alo);
    cudaGetSymbolAddress((void**)&mhi, g_mhi);
    cudaGetSymbolAddress((void**)&mlo, g_mlo);
    cudaGetSymbolAddress((void**)&fhi, g_fhi);
    cudaGetSymbolAddress((void**)&flo, g_flo);

    // ---- one mega split launch ----
    {
        SplitArgs a;
        const float* srcs[10] = {sa_wqkv, sa_wo, ca_wq, ca_wk, ca_wv, ca_wo, f_w1, f_w2, memory, tgt};
        long long sizes[10] = {
            (long long)LAYERS * 3 * E * E, (long long)LAYERS * E * E, (long long)LAYERS * E * E,
            (long long)LAYERS * E * E, (long long)LAYERS * E * E, (long long)LAYERS * E * E,
            (long long)LAYERS * FF * E, (long long)LAYERS * E * FF,
            (long long)MK_ROWS * E, (long long)MQ_ROWS * E};
        long long offs[8] = {OFF_WQKV, OFF_WO, OFF_WQ, OFF_WK, OFF_WV, OFF_WCO, OFF_W1, OFF_W2};
        a.cum[0] = 0;
        for (int s = 0; s < 10; s++) {
            a.src[s] = srcs[s];
            a.cpy[s] = nullptr;
            a.cum[s + 1] = a.cum[s] + sizes[s];
            if (s < 8)       { a.hi[s] = whi + offs[s]; a.lo[s] = wlo + offs[s]; }
            else if (s == 8) { a.hi[s] = mhi;           a.lo[s] = mlo; }
            else             { a.hi[s] = thi;           a.lo[s] = tlo; a.cpy[s] = t; }
        }
        long long total = a.cum[10];
        mega_split_kernel<<<(unsigned)((total + 255) / 256), 256>>>(a);
    }

    dim3 attn_grid((NQ + TQ - 1) / TQ, H, B);

    for (int l = 0; l < LAYERS; l++) {
        const size_t wEE = (size_t)l * E * E;
        const __nv_bfloat16* wqkv_h = whi + OFF_WQKV + (size_t)l * 3 * E * E;
        const __nv_bfloat16* wqkv_l = wlo + OFF_WQKV + (size_t)l * 3 * E * E;
        const float* bqkv = sa_bqkv + (size_t)l * 3 * E;
        const float* bo   = sa_bo + (size_t)l * E;
        const float* bq   = ca_bq + (size_t)l * E;
        const float* bk   = ca_bk + (size_t)l * E;
        const float* bv   = ca_bv + (size_t)l * E;
        const float* bco  = ca_bo + (size_t)l * E;
        const float* b1   = f_b1 + (size_t)l * FF;
        const float* b2   = f_b2 + (size_t)l * E;
        const float* g1   = ln1g + (size_t)l * E;
        const float* be1  = ln1b + (size_t)l * E;
        const float* g2   = ln2g + (size_t)l * E;
        const float* be2  = ln2b + (size_t)l * E;
        const float* g3   = ln3g + (size_t)l * E;
        const float* be3  = ln3b + (size_t)l * E;

        // --- self-attention ---
        tc_gemm(thi, tlo, wqkv_h, wqkv_l, bqkv, qkv, MQ_ROWS, 3 * E, E);
        flash_attn_kernel<<<attn_grid, 256>>>(qkv, 3 * E, qkv + E, qkv + 2 * E, 3 * E,
                                              NQ, NQ, nullptr, ahi, alo);
        tc_gemm(ahi, alo, whi + OFF_WO + wEE, wlo + OFF_WO + wEE, bo, proj, MQ_ROWS, E, E);
        ln_kernel<<<MQ_ROWS, E>>>(t, proj, g1, be1, t, thi, tlo);

        // --- cross-attention ---
        tc_gemm(mhi, mlo, whi + OFF_WK + wEE, wlo + OFF_WK + wEE, bk, kb, MK_ROWS, E, E);
        tc_gemm(mhi, mlo, whi + OFF_WV + wEE, wlo + OFF_WV + wEE, bv, vb, MK_ROWS, E, E);
        tc_gemm(thi, tlo, whi + OFF_WQ + wEE, wlo + OFF_WQ + wEE, bq, qb, MQ_ROWS, E, E);
        flash_attn_kernel<<<attn_grid, 256>>>(qb, E, kb, vb, E,
                                              NQ, NK, gmask, ahi, alo);
        tc_gemm(ahi, alo, whi + OFF_WCO + wEE, wlo + OFF_WCO + wEE, bco, proj, MQ_ROWS, E, E);
        ln_kernel<<<MQ_ROWS, E>>>(t, proj, g2, be2, t, thi, tlo);

        // --- FFN ---
        tc_gemm_relu_split(thi, tlo, whi + OFF_W1 + (size_t)l * FF * E, wlo + OFF_W1 + (size_t)l * FF * E,
                           b1, fhi, flo, MQ_ROWS, FF, E);
        tc_gemm(fhi, flo, whi + OFF_W2 + (size_t)l * E * FF, wlo + OFF_W2 + (size_t)l * E * FF,
                b2, proj, MQ_ROWS, E, FF);
        ln_kernel<<<MQ_ROWS, E>>>(t, proj, g3, be3, t, thi, tlo);
    }

    ln_kernel<<<MQ_ROWS, E>>>(t, nullptr, lnfg, lnfb, (float*)d_out, nullptr, nullptr);
}

// round 9
// speedup vs baseline: 2.0058x; 1.2570x over previous
#include <cuda_runtime.h>
#include <cuda_bf16.h>
#include <math.h>
#include <stdint.h>

// Problem constants
#define B   8
#define NQ  300
#define NK  4096
#define E   256
#define H   8
#define D   32
#define FF  2048
#define LAYERS 6
#define ATTN_SCALE 0.17677669529663687f

#define TQ 32      // attention query tile
#define CK 128     // attention key chunk

#define MQ_ROWS (B * NQ)   // 2400
#define MK_ROWS (B * NK)   // 32768

#if defined(__CUDA_ARCH_SPECIFIC__) || defined(__CUDA_ARCH_FEAT_SM103_ALL) || defined(__CUDA_ARCH_FEAT_SM100_ALL)
#define HAS_TC 1
#else
#define HAS_TC 0
#endif

// ---------------- fp32 scratch ----------------
__device__ float g_t[MQ_ROWS * E];
__device__ float g_qkv[MQ_ROWS * 3 * E];
__device__ float g_proj[MQ_ROWS * E];
__device__ float g_q[MQ_ROWS * E];
__device__ float g_k[MK_ROWS * E];
__device__ float g_v[MK_ROWS * E];

// ---------------- bf16 hi/lo scratch ----------------
#define OFF_WQKV 0
#define OFF_WO   1179648
#define OFF_WQ   1572864
#define OFF_WK   1966080
#define OFF_WV   2359296
#define OFF_WCO  2752512
#define OFF_W1   3145728
#define OFF_W2   6291456
#define W_TOTAL  9437184

__device__ __nv_bfloat16 g_whi[W_TOTAL];
__device__ __nv_bfloat16 g_wlo[W_TOTAL];
__device__ __nv_bfloat16 g_thi[MQ_ROWS * E],  g_tlo[MQ_ROWS * E];
__device__ __nv_bfloat16 g_ahi[MQ_ROWS * E],  g_alo[MQ_ROWS * E];
__device__ __nv_bfloat16 g_mhi[MK_ROWS * E],  g_mlo[MK_ROWS * E];
__device__ __nv_bfloat16 g_fhi[MQ_ROWS * FF], g_flo[MQ_ROWS * FF];

// ================= PTX helpers =================
__device__ __forceinline__ uint32_t smem_u32(const void* p) {
    uint32_t a;
    asm("{ .reg .u64 t; cvta.to.shared.u64 t, %1; cvt.u32.u64 %0, t; }" : "=r"(a) : "l"(p));
    return a;
}

// packed fp32x2 FMA (sm_100+; gated so generic PTX pass compiles)
__device__ __forceinline__ float2 ffma2(float2 a, float2 b, float2 c) {
#if HAS_TC
    float2 d;
    asm("{\n\t"
        ".reg .b64 ra, rb, rc, rd;\n\t"
        "mov.b64 ra, {%2, %3};\n\t"
        "mov.b64 rb, {%4, %5};\n\t"
        "mov.b64 rc, {%6, %7};\n\t"
        "fma.rn.f32x2 rd, ra, rb, rc;\n\t"
        "mov.b64 {%0, %1}, rd;\n\t"
        "}" : "=f"(d.x), "=f"(d.y)
            : "f"(a.x), "f"(a.y), "f"(b.x), "f"(b.y), "f"(c.x), "f"(c.y));
    return d;
#else
    return make_float2(fmaf(a.x, b.x, c.x), fmaf(a.y, b.y, c.y));
#endif
}

#if HAS_TC
__device__ __forceinline__ uint32_t elect_one() {
    uint32_t pred;
    asm volatile("{.reg .pred p; elect.sync _|p, 0xFFFFFFFF; selp.b32 %0, 1, 0, p;}" : "=r"(pred));
    return pred;
}
#define TC_ALLOC(sm, n)  asm volatile("tcgen05.alloc.cta_group::1.sync.aligned.shared::cta.b32 [%0], %1;" :: "r"((uint32_t)(sm)), "r"((uint32_t)(n)) : "memory")
#define TC_DEALLOC(t, n) asm volatile("tcgen05.dealloc.cta_group::1.sync.aligned.b32 %0, %1;" :: "r"(t), "r"((uint32_t)(n)))
#define TC_RELINQ()      asm volatile("tcgen05.relinquish_alloc_permit.cta_group::1.sync.aligned;")
#define TC_COMMIT(mb)    asm volatile("tcgen05.commit.cta_group::1.mbarrier::arrive::one.shared::cluster.b64 [%0];" :: "r"((uint32_t)(mb)) : "memory")
#define TC_WAIT_LD()     asm volatile("tcgen05.wait::ld.sync.aligned;" ::: "memory")
#define TC_FENCE_AFTER() asm volatile("tcgen05.fence::after_thread_sync;" ::: "memory")
#define FENCE_ASYNC()    asm volatile("fence.proxy.async.shared::cta;" ::: "memory")
#define MBAR_INIT(mb, c) asm volatile("mbarrier.init.shared.b64 [%0], %1;" :: "r"((uint32_t)(mb)), "r"((uint32_t)(c)) : "memory")

#define MBAR_WAIT(mb, ph) do { \
    uint32_t _m = (uint32_t)(mb), _p = (uint32_t)(ph), _d; \
    asm volatile("{.reg .pred p; mbarrier.try_wait.parity.acquire.cta.shared::cta.b64 p, [%1], %2; selp.b32 %0, 1, 0, p;}" \
        : "=r"(_d) : "r"(_m), "r"(_p) : "memory"); \
    if (!_d) { \
        asm volatile("{.reg .pred P1; WL_%=: mbarrier.try_wait.parity.acquire.cta.shared::cta.b64 P1, [%0], %1, 0x989680;" \
            "@P1 bra.uni WD_%=; bra.uni WL_%=; WD_%=: }" :: "r"(_m), "r"(_p) : "memory"); \
    } \
} while (0)

#define TC_LD_X32(r, addr) \
    asm volatile("tcgen05.ld.sync.aligned.32x32b.x32.b32 " \
        "{%0,%1,%2,%3,%4,%5,%6,%7,%8,%9,%10,%11,%12,%13,%14,%15," \
        "%16,%17,%18,%19,%20,%21,%22,%23,%24,%25,%26,%27,%28,%29,%30,%31}, [%32];" \
        : "=r"((r)[0]),"=r"((r)[1]),"=r"((r)[2]),"=r"((r)[3]),"=r"((r)[4]),"=r"((r)[5]),"=r"((r)[6]),"=r"((r)[7]), \
          "=r"((r)[8]),"=r"((r)[9]),"=r"((r)[10]),"=r"((r)[11]),"=r"((r)[12]),"=r"((r)[13]),"=r"((r)[14]),"=r"((r)[15]), \
          "=r"((r)[16]),"=r"((r)[17]),"=r"((r)[18]),"=r"((r)[19]),"=r"((r)[20]),"=r"((r)[21]),"=r"((r)[22]),"=r"((r)[23]), \
          "=r"((r)[24]),"=r"((r)[25]),"=r"((r)[26]),"=r"((r)[27]),"=r"((r)[28]),"=r"((r)[29]),"=r"((r)[30]),"=r"((r)[31]) \
        : "r"(addr))

__device__ __forceinline__ void mma_f16_ss(uint32_t d, uint64_t a, uint64_t b,
                                           uint32_t idesc, bool acc) {
    uint32_t e = acc ? 1u : 0u;
    asm volatile(
        "{\n\t.reg .pred p;\n\tsetp.ne.u32 p, %4, 0;\n\t"
        "tcgen05.mma.cta_group::1.kind::f16 [%0], %1, %2, %3, {%5, %5, %5, %5}, p;\n\t}"
        :: "r"(d), "l"(a), "l"(b), "r"(idesc), "r"(e), "r"(0u) : "memory");
}
#endif // HAS_TC

#define SW128(x) ((x) ^ (((x) >> 3) & 0x70))
static constexpr uint64_t DESC_BASE_SW128 =
    (uint64_t(2) << 61) | (uint64_t(1) << 46) | (uint64_t(64) << 32) | (uint64_t(1) << 16);
#define MK_DESC(a) (DESC_BASE_SW128 | ((uint64_t)((a) >> 4) & 0x3FFF))

// idesc: F32 accum, bf16 A/B, M=128, N=128
#define TC_IDESC ((1u << 4) | (1u << 7) | (1u << 10) | (16u << 17) | (8u << 24))

// ================= tcgen05 split-bf16 GEMM (double-buffered, 256 threads) =================
#define SMG_MBAR   0
#define SMG_TMEMP  16
#define SMG_BIAS   512
#define SMG_BUF0   1024
#define SMG_BUFSZ  65536
#define SMG_TOTAL  (1024 + 2 * 65536 + 1024)

template <int RELU, int SPLIT>
__global__ void __launch_bounds__(256, 1) __cluster_dims__(1, 1, 1)
tc_gemm_kernel(const __nv_bfloat16* __restrict__ Ahi, const __nv_bfloat16* __restrict__ Alo,
               const __nv_bfloat16* __restrict__ Whi, const __nv_bfloat16* __restrict__ Wlo,
               const float* __restrict__ bias,
               float* __restrict__ C,
               __nv_bfloat16* __restrict__ Chi, __nv_bfloat16* __restrict__ Clo,
               int M, int N, int K) {
    extern __shared__ __align__(16) char smem_raw[];
    char* smem = (char*)((((uintptr_t)smem_raw) + 1023) & ~(uintptr_t)1023);
    const uint32_t sb = smem_u32(smem);
    const int tid = threadIdx.x;
    const int wid = tid >> 5, lane = tid & 31;
    const int n0 = blockIdx.x * 128;
    const int m0 = blockIdx.y * 128;
    (void)sb; (void)wid; (void)lane;

#if HAS_TC
    if (wid == 0) {
        TC_ALLOC(sb + SMG_TMEMP, 128);
        TC_RELINQ();
    }
    if (tid == 0) { MBAR_INIT(sb + SMG_MBAR, 1); }
    if (tid < 128) ((float*)(smem + SMG_BIAS))[tid] = bias[n0 + tid];

    const int nchunks = K >> 6;

// 4096 uint4 across 256 threads = 16 iterations
#define STAGE_CHUNK(bsel, kc) do { \
    const int kel = (kc) * 64; \
    const uint32_t bbase = SMG_BUF0 + (bsel) * SMG_BUFSZ; \
    _Pragma("unroll") \
    for (int it = 0; it < 16; it++) { \
        int idx = it * 256 + tid; \
        int tile = idx >> 10; \
        int r = (idx >> 3) & 127; \
        int c16 = idx & 7; \
        uint4 val = make_uint4(0, 0, 0, 0); \
        if (tile < 2) { \
            int m = m0 + r; \
            if (m < M) { \
                const __nv_bfloat16* src = (tile == 0) ? Ahi : Alo; \
                val = *(const uint4*)&src[(size_t)m * K + kel + c16 * 8]; \
            } \
        } else { \
            int n = n0 + r; \
            const __nv_bfloat16* src = (tile == 2) ? Whi : Wlo; \
            val = *(const uint4*)&src[(size_t)n * K + kel + c16 * 8]; \
        } \
        uint32_t off = bbase + tile * 16384 + SW128((uint32_t)(r * 128 + c16 * 16)); \
        *(uint4*)(smem + off) = val; \
    } \
} while (0)

    STAGE_CHUNK(0, 0);
    __syncthreads();

    uint32_t tmem;
    asm volatile("ld.shared.b32 %0, [%1];" : "=r"(tmem) : "r"(sb + SMG_TMEMP));

    int phase = 0;
    for (int kc = 0; kc < nchunks; kc++) {
        const int bsel = kc & 1;
        const uint32_t bbase = sb + SMG_BUF0 + bsel * SMG_BUFSZ;
        if (wid == 0) {
            if (elect_one()) {
                FENCE_ASYNC();
                const uint64_t dAhi = MK_DESC(bbase);
                const uint64_t dAlo = MK_DESC(bbase + 16384);
                const uint64_t dBhi = MK_DESC(bbase + 32768);
                const uint64_t dBlo = MK_DESC(bbase + 49152);
                bool first = (kc == 0);
#pragma unroll
                for (int ks = 0; ks < 4; ks++)
                    mma_f16_ss(tmem, dAhi + ks * 2, dBhi + ks * 2, TC_IDESC, !(first && ks == 0));
#pragma unroll
                for (int ks = 0; ks < 4; ks++)
                    mma_f16_ss(tmem, dAhi + ks * 2, dBlo + ks * 2, TC_IDESC, true);
#pragma unroll
                for (int ks = 0; ks < 4; ks++)
                    mma_f16_ss(tmem, dAlo + ks * 2, dBhi + ks * 2, TC_IDESC, true);
                TC_COMMIT(sb + SMG_MBAR);
            }
        }
        if (kc + 1 < nchunks) {
            STAGE_CHUNK((kc + 1) & 1, kc + 1);
        }
        MBAR_WAIT(sb + SMG_MBAR, phase);
        phase ^= 1;
        __syncthreads();
    }
#undef STAGE_CHUNK

    TC_FENCE_AFTER();

    // epilogue: warps 0-3 own the 128 TMEM lanes
    if (wid < 4) {
        const float* bsm = (const float*)(smem + SMG_BIAS);
        const int m = m0 + wid * 32 + lane;
#pragma unroll
        for (int cc = 0; cc < 4; cc++) {
            uint32_t dr[32];
            TC_LD_X32(dr, tmem + cc * 32);
            TC_WAIT_LD();
            if (m < M) {
                const int nb = n0 + cc * 32;
                if (SPLIT) {
#pragma unroll
                    for (int j2 = 0; j2 < 16; j2++) {
                        float v0 = __uint_as_float(dr[j2 * 2 + 0]) + bsm[cc * 32 + j2 * 2 + 0];
                        float v1 = __uint_as_float(dr[j2 * 2 + 1]) + bsm[cc * 32 + j2 * 2 + 1];
                        if (RELU) { v0 = fmaxf(v0, 0.f); v1 = fmaxf(v1, 0.f); }
                        __nv_bfloat16 h0 = __float2bfloat16_rn(v0);
                        __nv_bfloat16 h1 = __float2bfloat16_rn(v1);
                        __nv_bfloat16 l0 = __float2bfloat16_rn(v0 - __bfloat162float(h0));
                        __nv_bfloat16 l1 = __float2bfloat16_rn(v1 - __bfloat162float(h1));
                        *(__nv_bfloat162*)&Chi[(size_t)m * N + nb + j2 * 2] = __nv_bfloat162(h0, h1);
                        *(__nv_bfloat162*)&Clo[(size_t)m * N + nb + j2 * 2] = __nv_bfloat162(l0, l1);
                    }
                } else {
                    float* crow = &C[(size_t)m * N + nb];
#pragma unroll
                    for (int c4 = 0; c4 < 8; c4++) {
                        float4 o;
                        o.x = __uint_as_float(dr[c4 * 4 + 0]) + bsm[cc * 32 + c4 * 4 + 0];
                        o.y = __uint_as_float(dr[c4 * 4 + 1]) + bsm[cc * 32 + c4 * 4 + 1];
                        o.z = __uint_as_float(dr[c4 * 4 + 2]) + bsm[cc * 32 + c4 * 4 + 2];
                        o.w = __uint_as_float(dr[c4 * 4 + 3]) + bsm[cc * 32 + c4 * 4 + 3];
                        if (RELU) {
                            o.x = fmaxf(o.x, 0.f); o.y = fmaxf(o.y, 0.f);
                            o.z = fmaxf(o.z, 0.f); o.w = fmaxf(o.w, 0.f);
                        }
                        *(float4*)&crow[c4 * 4] = o;
                    }
                }
            }
        }
    }

    __syncthreads();
    if (wid == 0) { TC_DEALLOC(tmem, 128); }
#else
    // generic-PTX fallback (insurance)
    const int half = tid >> 7;            // 0 or 1
    const int m = m0 + (tid & 127);
    if (m < M) {
        for (int cg = half * 2; cg < half * 2 + 2; cg++) {
            float acc[32];
#pragma unroll
            for (int j = 0; j < 32; j++) acc[j] = bias[n0 + cg * 32 + j];
            for (int k = 0; k < K; k++) {
                float a = __bfloat162float(Ahi[(size_t)m * K + k]) +
                          __bfloat162float(Alo[(size_t)m * K + k]);
#pragma unroll
                for (int j = 0; j < 32; j++) {
                    int n = n0 + cg * 32 + j;
                    float w = __bfloat162float(Whi[(size_t)n * K + k]) +
                              __bfloat162float(Wlo[(size_t)n * K + k]);
                    acc[j] += a * w;
                }
            }
#pragma unroll
            for (int j = 0; j < 32; j++) {
                float v = acc[j];
                if (RELU) v = fmaxf(v, 0.f);
                int n = n0 + cg * 32 + j;
                if (SPLIT) {
                    __nv_bfloat16 h = __float2bfloat16_rn(v);
                    Chi[(size_t)m * N + n] = h;
                    Clo[(size_t)m * N + n] = __float2bfloat16_rn(v - __bfloat162float(h));
                } else {
                    C[(size_t)m * N + n] = v;
                }
            }
        }
    }
#endif
}

// ================= mega split =================
struct SplitArgs {
    const float* src[10];
    __nv_bfloat16* hi[10];
    __nv_bfloat16* lo[10];
    float* cpy[10];
    long long cum[11];
};

__global__ void mega_split_kernel(SplitArgs a) {
    long long i = (long long)blockIdx.x * blockDim.x + threadIdx.x;
    if (i >= a.cum[10]) return;
    int s = 0;
#pragma unroll
    for (int k = 0; k < 10; k++)
        if (i >= a.cum[k + 1]) s = k + 1;
    long long off = i - a.cum[s];
    float v = a.src[s][off];
    __nv_bfloat16 h = __float2bfloat16_rn(v);
    a.hi[s][off] = h;
    a.lo[s][off] = __float2bfloat16_rn(v - __bfloat162float(h));
    if (a.cpy[s]) a.cpy[s][off] = v;
}

// ================= unified tiled flash attention (SA + CA) =================
__global__ void __launch_bounds__(256, 2)
flash_attn_kernel(const float* __restrict__ Qp, int qstride,
                  const float* __restrict__ Kp, const float* __restrict__ Vp, int kvstride,
                  int nq, int nk,
                  const int* __restrict__ mask,
                  __nv_bfloat16* __restrict__ ohi, __nv_bfloat16* __restrict__ olo) {
    const int qt = blockIdx.x, h = blockIdx.y, b = blockIdx.z;
    const int tid = threadIdx.x;
    const int w = tid >> 5, lane = tid & 31;

    __shared__ __align__(16) float Ks[CK * 36];
    __shared__ __align__(16) float Vs[CK * 36];
    __shared__ __align__(16) float Qs[TQ * 36];
    __shared__ __align__(16) float Psm[8][4][CK];

    for (int i = tid; i < TQ * 8; i += 256) {
        int ql = i >> 3, d4 = i & 7;
        int qg = qt * TQ + ql;
        if (qg >= nq) qg = nq - 1;
        *(float4*)&Qs[ql * 36 + d4 * 4] =
            *(const float4*)&Qp[((size_t)(b * nq + qg)) * qstride + h * D + d4 * 4];
    }
    __syncthreads();

    int qg_[4];
    const int* mrow[4];
#pragma unroll
    for (int sub = 0; sub < 4; sub++) {
        int qg = qt * TQ + w * 4 + sub;
        qg_[sub] = qg;
        int qc = (qg < nq) ? qg : nq - 1;
        mrow[sub] = mask ? (mask + ((size_t)(b * nq + qc)) * nk) : nullptr;
    }

    float mv[4] = {-INFINITY, -INFINITY, -INFINITY, -INFINITY};
    float sv[4] = {0.f, 0.f, 0.f, 0.f};
    float2 av2[4] = {{0.f, 0.f}, {0.f, 0.f}, {0.f, 0.f}, {0.f, 0.f}};

    for (int k0 = 0; k0 < nk; k0 += CK) {
        for (int i = tid; i < CK * 8; i += 256) {
            int j = i >> 3, d4 = i & 7;
            int kg = k0 + j;
            float4 kv = make_float4(0.f, 0.f, 0.f, 0.f);
            float4 vv = make_float4(0.f, 0.f, 0.f, 0.f);
            if (kg < nk) {
                size_t base = ((size_t)(b * nk + kg)) * kvstride + h * D + d4 * 4;
                kv = *(const float4*)&Kp[base];
                vv = *(const float4*)&Vp[base];
            }
            *(float4*)&Ks[j * 36 + d4 * 4] = kv;
            *(float4*)&Vs[j * 36 + d4 * 4] = vv;
        }
        __syncthreads();

        // ---- score phase ----
        float sc[4][4];
#pragma unroll
        for (int c = 0; c < 4; c++) {
            const int key = c * 32 + lane;
            const bool kval = (k0 + key < nk);
            float4 k4[8];
#pragma unroll
            for (int d4 = 0; d4 < 8; d4++)
                k4[d4] = *(const float4*)&Ks[key * 36 + d4 * 4];
#pragma unroll
            for (int sub = 0; sub < 4; sub++) {
                const int ql = w * 4 + sub;
                float2 s2 = make_float2(0.f, 0.f);
#pragma unroll
                for (int d4 = 0; d4 < 8; d4++) {
                    float4 q4 = *(const float4*)&Qs[ql * 36 + d4 * 4];
                    s2 = ffma2(make_float2(k4[d4].x, k4[d4].y), make_float2(q4.x, q4.y), s2);
                    s2 = ffma2(make_float2(k4[d4].z, k4[d4].w), make_float2(q4.z, q4.w), s2);
                }
                float s = s2.x + s2.y;
                bool val = kval && (!mask || (mrow[sub][k0 + key] != 0));
                sc[sub][c] = val ? (s * ATTN_SCALE) : -INFINITY;
            }
        }

        // ---- online softmax ----
#pragma unroll
        for (int sub = 0; sub < 4; sub++) {
            float cmax = fmaxf(fmaxf(sc[sub][0], sc[sub][1]), fmaxf(sc[sub][2], sc[sub][3]));
#pragma unroll
            for (int o = 16; o > 0; o >>= 1)
                cmax = fmaxf(cmax, __shfl_xor_sync(0xffffffff, cmax, o));
            float mOld = mv[sub];
            float mNew = fmaxf(mOld, cmax);
            float factor, psum = 0.f;
            if (mNew == -INFINITY) {
                factor = 1.f;
#pragma unroll
                for (int c = 0; c < 4; c++) Psm[w][sub][c * 32 + lane] = 0.f;
            } else {
                factor = __expf(mOld - mNew);
#pragma unroll
                for (int c = 0; c < 4; c++) {
                    float p = (sc[sub][c] == -INFINITY) ? 0.f : __expf(sc[sub][c] - mNew);
                    psum += p;
                    Psm[w][sub][c * 32 + lane] = p;
                }
            }
#pragma unroll
            for (int o = 16; o > 0; o >>= 1)
                psum += __shfl_xor_sync(0xffffffff, psum, o);
            sv[sub] = sv[sub] * factor + psum;
            mv[sub] = mNew;
            av2[sub].x *= factor;
            av2[sub].y *= factor;
        }
        __syncwarp();

        // ---- V phase ----
#pragma unroll 4
        for (int j4 = 0; j4 < 32; j4++) {
            float v0 = Vs[(j4 * 4 + 0) * 36 + lane];
            float v1 = Vs[(j4 * 4 + 1) * 36 + lane];
            float v2 = Vs[(j4 * 4 + 2) * 36 + lane];
            float v3 = Vs[(j4 * 4 + 3) * 36 + lane];
#pragma unroll
            for (int sub = 0; sub < 4; sub++) {
                float4 p = *(const float4*)&Psm[w][sub][j4 * 4];
                av2[sub] = ffma2(make_float2(p.x, p.y), make_float2(v0, v1), av2[sub]);
                av2[sub] = ffma2(make_float2(p.z, p.w), make_float2(v2, v3), av2[sub]);
            }
        }
        __syncthreads();
    }

#pragma unroll
    for (int sub = 0; sub < 4; sub++) {
        if (qg_[sub] < nq) {
            float a = av2[sub].x + av2[sub].y;
            float inv = (sv[sub] > 0.f) ? 1.f / sv[sub] : 0.f;
            float o = a * inv;
            size_t idx = (size_t)(b * nq + qg_[sub]) * E + h * D + lane;
            __nv_bfloat16 hh = __float2bfloat16_rn(o);
            ohi[idx] = hh;
            olo[idx] = __float2bfloat16_rn(o - __bfloat162float(hh));
        }
    }
}

// ================= LayerNorm =================
__global__ void ln_kernel(const float* __restrict__ x,
                          const float* __restrict__ res,
                          const float* __restrict__ gamma,
                          const float* __restrict__ beta,
                          float* __restrict__ out,
                          __nv_bfloat16* __restrict__ ohi,
                          __nv_bfloat16* __restrict__ olo) {
    const int row = blockIdx.x;
    const int tid = threadIdx.x;
    const int lane = tid & 31, wid = tid >> 5;
    __shared__ float r1[8], r2[8];

    size_t idx = (size_t)row * E + tid;
    float v = x[idx];
    if (res) v += res[idx];

    float s = v;
#pragma unroll
    for (int o = 16; o > 0; o >>= 1) s += __shfl_xor_sync(0xffffffff, s, o);
    if (lane == 0) r1[wid] = s;
    __syncthreads();
    float tot = 0.f;
#pragma unroll
    for (int i = 0; i < 8; i++) tot += r1[i];
    float mean = tot * (1.f / E);

    float d = v - mean;
    float s2 = d * d;
#pragma unroll
    for (int o = 16; o > 0; o >>= 1) s2 += __shfl_xor_sync(0xffffffff, s2, o);
    if (lane == 0) r2[wid] = s2;
    __syncthreads();
    float tv = 0.f;
#pragma unroll
    for (int i = 0; i < 8; i++) tv += r2[i];
    float o_ = d * rsqrtf(tv * (1.f / E) + 1e-5f) * gamma[tid] + beta[tid];
    out[idx] = o_;
    if (ohi) {
        __nv_bfloat16 h = __float2bfloat16_rn(o_);
        ohi[idx] = h;
        olo[idx] = __float2bfloat16_rn(o_ - __bfloat162float(h));
    }
}

// ================= host side =================
static inline void tc_gemm(const __nv_bfloat16* Ahi, const __nv_bfloat16* Alo,
                           const __nv_bfloat16* Whi, const __nv_bfloat16* Wlo,
                           const float* bias, float* C, int M, int N, int K) {
    dim3 grid(N / 128, (M + 127) / 128);
    tc_gemm_kernel<0, 0><<<grid, 256, SMG_TOTAL>>>(Ahi, Alo, Whi, Wlo, bias, C, nullptr, nullptr, M, N, K);
}
static inline void tc_gemm_relu_split(const __nv_bfloat16* Ahi, const __nv_bfloat16* Alo,
                                      const __nv_bfloat16* Whi, const __nv_bfloat16* Wlo,
                                      const float* bias, __nv_bfloat16* Chi, __nv_bfloat16* Clo,
                                      int M, int N, int K) {
    dim3 grid(N / 128, (M + 127) / 128);
    tc_gemm_kernel<1, 1><<<grid, 256, SMG_TOTAL>>>(Ahi, Alo, Whi, Wlo, bias, nullptr, Chi, Clo, M, N, K);
}

extern "C" void kernel_launch(void* const* d_in, const int* in_sizes, int n_in,
                              void* d_out, int out_size) {
    cudaFuncSetAttribute(tc_gemm_kernel<0, 0>, cudaFuncAttributeMaxDynamicSharedMemorySize, SMG_TOTAL);
    cudaFuncSetAttribute(tc_gemm_kernel<1, 1>, cudaFuncAttributeMaxDynamicSharedMemorySize, SMG_TOTAL);

    const float* tgt      = (const float*)d_in[0];
    const float* memory   = (const float*)d_in[1];
    const int*   gmask    = (const int*)d_in[2];
    const float* sa_wqkv  = (const float*)d_in[3];
    const float* sa_bqkv  = (const float*)d_in[4];
    const float* sa_wo    = (const float*)d_in[5];
    const float* sa_bo    = (const float*)d_in[6];
    const float* ca_wq    = (const float*)d_in[7];
    const float* ca_bq    = (const float*)d_in[8];
    const float* ca_wk    = (const float*)d_in[9];
    const float* ca_bk    = (const float*)d_in[10];
    const float* ca_wv    = (const float*)d_in[11];
    const float* ca_bv    = (const float*)d_in[12];
    const float* ca_wo    = (const float*)d_in[13];
    const float* ca_bo    = (const float*)d_in[14];
    const float* f_w1     = (const float*)d_in[15];
    const float* f_b1     = (const float*)d_in[16];
    const float* f_w2     = (const float*)d_in[17];
    const float* f_b2     = (const float*)d_in[18];
    const float* ln1g     = (const float*)d_in[19];
    const float* ln1b     = (const float*)d_in[20];
    const float* ln2g     = (const float*)d_in[21];
    const float* ln2b     = (const float*)d_in[22];
    const float* ln3g     = (const float*)d_in[23];
    const float* ln3b     = (const float*)d_in[24];
    const float* lnfg     = (const float*)d_in[25];
    const float* lnfb     = (const float*)d_in[26];

    float *t, *qkv, *proj, *qb, *kb, *vb;
    cudaGetSymbolAddress((void**)&t,    g_t);
    cudaGetSymbolAddress((void**)&qkv,  g_qkv);
    cudaGetSymbolAddress((void**)&proj, g_proj);
    cudaGetSymbolAddress((void**)&qb,   g_q);
    cudaGetSymbolAddress((void**)&kb,   g_k);
    cudaGetSymbolAddress((void**)&vb,   g_v);

    __nv_bfloat16 *whi, *wlo, *thi, *tlo, *ahi, *alo, *mhi, *mlo, *fhi, *flo;
    cudaGetSymbolAddress((void**)&whi, g_whi);
    cudaGetSymbolAddress((void**)&wlo, g_wlo);
    cudaGetSymbolAddress((void**)&thi, g_thi);
    cudaGetSymbolAddress((void**)&tlo, g_tlo);
    cudaGetSymbolAddress((void**)&ahi, g_ahi);
    cudaGetSymbolAddress((void**)&alo, g_alo);
    cudaGetSymbolAddress((void**)&mhi, g_mhi);
    cudaGetSymbolAddress((void**)&mlo, g_mlo);
    cudaGetSymbolAddress((void**)&fhi, g_fhi);
    cudaGetSymbolAddress((void**)&flo, g_flo);

    // ---- one mega split launch ----
    {
        SplitArgs a;
        const float* srcs[10] = {sa_wqkv, sa_wo, ca_wq, ca_wk, ca_wv, ca_wo, f_w1, f_w2, memory, tgt};
        long long sizes[10] = {
            (long long)LAYERS * 3 * E * E, (long long)LAYERS * E * E, (long long)LAYERS * E * E,
            (long long)LAYERS * E * E, (long long)LAYERS * E * E, (long long)LAYERS * E * E,
            (long long)LAYERS * FF * E, (long long)LAYERS * E * FF,
            (long long)MK_ROWS * E, (long long)MQ_ROWS * E};
        long long offs[8] = {OFF_WQKV, OFF_WO, OFF_WQ, OFF_WK, OFF_WV, OFF_WCO, OFF_W1, OFF_W2};
        a.cum[0] = 0;
        for (int s = 0; s < 10; s++) {
            a.src[s] = srcs[s];
            a.cpy[s] = nullptr;
            a.cum[s + 1] = a.cum[s] + sizes[s];
            if (s < 8)       { a.hi[s] = whi + offs[s]; a.lo[s] = wlo + offs[s]; }
            else if (s == 8) { a.hi[s] = mhi;           a.lo[s] = mlo; }
            else             { a.hi[s] = thi;           a.lo[s] = tlo; a.cpy[s] = t; }
        }
        long long total = a.cum[10];
        mega_split_kernel<<<(unsigned)((total + 255) / 256), 256>>>(a);
    }

    dim3 attn_grid((NQ + TQ - 1) / TQ, H, B);

    for (int l = 0; l < LAYERS; l++) {
        const size_t wEE = (size_t)l * E * E;
        const __nv_bfloat16* wqkv_h = whi + OFF_WQKV + (size_t)l * 3 * E * E;
        const __nv_bfloat16* wqkv_l = wlo + OFF_WQKV + (size_t)l * 3 * E * E;
        const float* bqkv = sa_bqkv + (size_t)l * 3 * E;
        const float* bo   = sa_bo + (size_t)l * E;
        const float* bq   = ca_bq + (size_t)l * E;
        const float* bk   = ca_bk + (size_t)l * E;
        const float* bv   = ca_bv + (size_t)l * E;
        const float* bco  = ca_bo + (size_t)l * E;
        const float* b1   = f_b1 + (size_t)l * FF;
        const float* b2   = f_b2 + (size_t)l * E;
        const float* g1   = ln1g + (size_t)l * E;
        const float* be1  = ln1b + (size_t)l * E;
        const float* g2   = ln2g + (size_t)l * E;
        const float* be2  = ln2b + (size_t)l * E;
        const float* g3   = ln3g + (size_t)l * E;
        const float* be3  = ln3b + (size_t)l * E;

        // --- self-attention ---
        tc_gemm(thi, tlo, wqkv_h, wqkv_l, bqkv, qkv, MQ_ROWS, 3 * E, E);
        flash_attn_kernel<<<attn_grid, 256>>>(qkv, 3 * E, qkv + E, qkv + 2 * E, 3 * E,
                                              NQ, NQ, nullptr, ahi, alo);
        tc_gemm(ahi, alo, whi + OFF_WO + wEE, wlo + OFF_WO + wEE, bo, proj, MQ_ROWS, E, E);
        ln_kernel<<<MQ_ROWS, E>>>(t, proj, g1, be1, t, thi, tlo);

        // --- cross-attention ---
        tc_gemm(mhi, mlo, whi + OFF_WK + wEE, wlo + OFF_WK + wEE, bk, kb, MK_ROWS, E, E);
        tc_gemm(mhi, mlo, whi + OFF_WV + wEE, wlo + OFF_WV + wEE, bv, vb, MK_ROWS, E, E);
        tc_gemm(thi, tlo, whi + OFF_WQ + wEE, wlo + OFF_WQ + wEE, bq, qb, MQ_ROWS, E, E);
        flash_attn_kernel<<<attn_grid, 256>>>(qb, E, kb, vb, E,
                                              NQ, NK, gmask, ahi, alo);
        tc_gemm(ahi, alo, whi + OFF_WCO + wEE, wlo + OFF_WCO + wEE, bco, proj, MQ_ROWS, E, E);
        ln_kernel<<<MQ_ROWS, E>>>(t, proj, g2, be2, t, thi, tlo);

        // --- FFN ---
        tc_gemm_relu_split(thi, tlo, whi + OFF_W1 + (size_t)l * FF * E, wlo + OFF_W1 + (size_t)l * FF * E,
                           b1, fhi, flo, MQ_ROWS, FF, E);
        tc_gemm(fhi, flo, whi + OFF_W2 + (size_t)l * E * FF, wlo + OFF_W2 + (size_t)l * E * FF,
                b2, proj, MQ_ROWS, E, FF);
        ln_kernel<<<MQ_ROWS, E>>>(t, proj, g3, be3, t, thi, tlo);
    }

    ln_kernel<<<MQ_ROWS, E>>>(t, nullptr, lnfg, lnfb, (float*)d_out, nullptr, nullptr);
}

// round 10
// speedup vs baseline: 2.1165x; 1.0552x over previous
#include <cuda_runtime.h>
#include <cuda_bf16.h>
#include <math.h>
#include <stdint.h>

// Problem constants
#define B   8
#define NQ  300
#define NK  4096
#define E   256
#define H   8
#define D   32
#define FF  2048
#define LAYERS 6
#define ATTN_SCALE 0.17677669529663687f

#define TQ 32      // attention query tile
#define CK 128     // attention key chunk

#define MQ_ROWS (B * NQ)   // 2400
#define MK_ROWS (B * NK)   // 32768

#if defined(__CUDA_ARCH_SPECIFIC__) || defined(__CUDA_ARCH_FEAT_SM103_ALL) || defined(__CUDA_ARCH_FEAT_SM100_ALL)
#define HAS_TC 1
#else
#define HAS_TC 0
#endif

// ---------------- fp32 scratch ----------------
__device__ float g_t[MQ_ROWS * E];
__device__ float g_qkv[MQ_ROWS * 3 * E];
__device__ float g_proj[MQ_ROWS * E];
__device__ float g_q[MQ_ROWS * E];
__device__ float g_k6[LAYERS * MK_ROWS * E];   // all-layer CA K
__device__ float g_v6[LAYERS * MK_ROWS * E];   // all-layer CA V

// ---------------- bf16 hi/lo scratch ----------------
#define OFF_WQKV 0
#define OFF_WO   1179648
#define OFF_WQ   1572864
#define OFF_WK   1966080
#define OFF_WV   2359296
#define OFF_WCO  2752512
#define OFF_W1   3145728
#define OFF_W2   6291456
#define W_TOTAL  9437184

__device__ __nv_bfloat16 g_whi[W_TOTAL];
__device__ __nv_bfloat16 g_wlo[W_TOTAL];
__device__ __nv_bfloat16 g_thi[MQ_ROWS * E],  g_tlo[MQ_ROWS * E];
__device__ __nv_bfloat16 g_ahi[MQ_ROWS * E],  g_alo[MQ_ROWS * E];
__device__ __nv_bfloat16 g_mhi[MK_ROWS * E],  g_mlo[MK_ROWS * E];
__device__ __nv_bfloat16 g_fhi[MQ_ROWS * FF], g_flo[MQ_ROWS * FF];

// ================= PTX helpers =================
__device__ __forceinline__ uint32_t smem_u32(const void* p) {
    uint32_t a;
    asm("{ .reg .u64 t; cvta.to.shared.u64 t, %1; cvt.u32.u64 %0, t; }" : "=r"(a) : "l"(p));
    return a;
}

__device__ __forceinline__ float2 ffma2(float2 a, float2 b, float2 c) {
#if HAS_TC
    float2 d;
    asm("{\n\t"
        ".reg .b64 ra, rb, rc, rd;\n\t"
        "mov.b64 ra, {%2, %3};\n\t"
        "mov.b64 rb, {%4, %5};\n\t"
        "mov.b64 rc, {%6, %7};\n\t"
        "fma.rn.f32x2 rd, ra, rb, rc;\n\t"
        "mov.b64 {%0, %1}, rd;\n\t"
        "}" : "=f"(d.x), "=f"(d.y)
            : "f"(a.x), "f"(a.y), "f"(b.x), "f"(b.y), "f"(c.x), "f"(c.y));
    return d;
#else
    return make_float2(fmaf(a.x, b.x, c.x), fmaf(a.y, b.y, c.y));
#endif
}

#if HAS_TC
__device__ __forceinline__ uint32_t elect_one() {
    uint32_t pred;
    asm volatile("{.reg .pred p; elect.sync _|p, 0xFFFFFFFF; selp.b32 %0, 1, 0, p;}" : "=r"(pred));
    return pred;
}
#define TC_ALLOC(sm, n)  asm volatile("tcgen05.alloc.cta_group::1.sync.aligned.shared::cta.b32 [%0], %1;" :: "r"((uint32_t)(sm)), "r"((uint32_t)(n)) : "memory")
#define TC_DEALLOC(t, n) asm volatile("tcgen05.dealloc.cta_group::1.sync.aligned.b32 %0, %1;" :: "r"(t), "r"((uint32_t)(n)))
#define TC_RELINQ()      asm volatile("tcgen05.relinquish_alloc_permit.cta_group::1.sync.aligned;")
#define TC_COMMIT(mb)    asm volatile("tcgen05.commit.cta_group::1.mbarrier::arrive::one.shared::cluster.b64 [%0];" :: "r"((uint32_t)(mb)) : "memory")
#define TC_WAIT_LD()     asm volatile("tcgen05.wait::ld.sync.aligned;" ::: "memory")
#define TC_FENCE_AFTER() asm volatile("tcgen05.fence::after_thread_sync;" ::: "memory")
#define FENCE_ASYNC()    asm volatile("fence.proxy.async.shared::cta;" ::: "memory")
#define MBAR_INIT(mb, c) asm volatile("mbarrier.init.shared.b64 [%0], %1;" :: "r"((uint32_t)(mb)), "r"((uint32_t)(c)) : "memory")

#define MBAR_WAIT(mb, ph) do { \
    uint32_t _m = (uint32_t)(mb), _p = (uint32_t)(ph), _d; \
    asm volatile("{.reg .pred p; mbarrier.try_wait.parity.acquire.cta.shared::cta.b64 p, [%1], %2; selp.b32 %0, 1, 0, p;}" \
        : "=r"(_d) : "r"(_m), "r"(_p) : "memory"); \
    if (!_d) { \
        asm volatile("{.reg .pred P1; WL_%=: mbarrier.try_wait.parity.acquire.cta.shared::cta.b64 P1, [%0], %1, 0x989680;" \
            "@P1 bra.uni WD_%=; bra.uni WL_%=; WD_%=: }" :: "r"(_m), "r"(_p) : "memory"); \
    } \
} while (0)

#define TC_LD_X32(r, addr) \
    asm volatile("tcgen05.ld.sync.aligned.32x32b.x32.b32 " \
        "{%0,%1,%2,%3,%4,%5,%6,%7,%8,%9,%10,%11,%12,%13,%14,%15," \
        "%16,%17,%18,%19,%20,%21,%22,%23,%24,%25,%26,%27,%28,%29,%30,%31}, [%32];" \
        : "=r"((r)[0]),"=r"((r)[1]),"=r"((r)[2]),"=r"((r)[3]),"=r"((r)[4]),"=r"((r)[5]),"=r"((r)[6]),"=r"((r)[7]), \
          "=r"((r)[8]),"=r"((r)[9]),"=r"((r)[10]),"=r"((r)[11]),"=r"((r)[12]),"=r"((r)[13]),"=r"((r)[14]),"=r"((r)[15]), \
          "=r"((r)[16]),"=r"((r)[17]),"=r"((r)[18]),"=r"((r)[19]),"=r"((r)[20]),"=r"((r)[21]),"=r"((r)[22]),"=r"((r)[23]), \
          "=r"((r)[24]),"=r"((r)[25]),"=r"((r)[26]),"=r"((r)[27]),"=r"((r)[28]),"=r"((r)[29]),"=r"((r)[30]),"=r"((r)[31]) \
        : "r"(addr))

__device__ __forceinline__ void mma_f16_ss(uint32_t d, uint64_t a, uint64_t b,
                                           uint32_t idesc, bool acc) {
    uint32_t e = acc ? 1u : 0u;
    asm volatile(
        "{\n\t.reg .pred p;\n\tsetp.ne.u32 p, %4, 0;\n\t"
        "tcgen05.mma.cta_group::1.kind::f16 [%0], %1, %2, %3, {%5, %5, %5, %5}, p;\n\t}"
        :: "r"(d), "l"(a), "l"(b), "r"(idesc), "r"(e), "r"(0u) : "memory");
}
#endif // HAS_TC

#define SW128(x) ((x) ^ (((x) >> 3) & 0x70))
static constexpr uint64_t DESC_BASE_SW128 =
    (uint64_t(2) << 61) | (uint64_t(1) << 46) | (uint64_t(64) << 32) | (uint64_t(1) << 16);
#define MK_DESC(a) (DESC_BASE_SW128 | ((uint64_t)((a) >> 4) & 0x3FFF))

#define TC_IDESC ((1u << 4) | (1u << 7) | (1u << 10) | (16u << 17) | (8u << 24))

// ================= tcgen05 split-bf16 GEMM (double-buffered, 256 threads, layer-batched) ===
#define SMG_MBAR   0
#define SMG_TMEMP  16
#define SMG_BIAS   512
#define SMG_BUF0   1024
#define SMG_BUFSZ  65536
#define SMG_TOTAL  (1024 + 2 * 65536 + 1024)

template <int RELU, int SPLIT>
__global__ void __launch_bounds__(256, 1) __cluster_dims__(1, 1, 1)
tc_gemm_kernel(const __nv_bfloat16* __restrict__ Ahi, const __nv_bfloat16* __restrict__ Alo,
               const __nv_bfloat16* __restrict__ Whi, const __nv_bfloat16* __restrict__ Wlo,
               const float* __restrict__ bias,
               float* __restrict__ C,
               __nv_bfloat16* __restrict__ Chi, __nv_bfloat16* __restrict__ Clo,
               int M, int N, int K,
               size_t wStride, size_t biasStride, size_t cStride) {
    extern __shared__ __align__(16) char smem_raw[];
    char* smem = (char*)((((uintptr_t)smem_raw) + 1023) & ~(uintptr_t)1023);
    const uint32_t sb = smem_u32(smem);
    const int tid = threadIdx.x;
    const int wid = tid >> 5, lane = tid & 31;
    const int n0 = blockIdx.x * 128;
    const int m0 = blockIdx.y * 128;
    const int lz = blockIdx.z;
    Whi  += (size_t)lz * wStride;
    Wlo  += (size_t)lz * wStride;
    bias += (size_t)lz * biasStride;
    if (C)   C   += (size_t)lz * cStride;
    if (Chi) { Chi += (size_t)lz * cStride; Clo += (size_t)lz * cStride; }
    (void)sb; (void)wid; (void)lane;

#if HAS_TC
    if (wid == 0) {
        TC_ALLOC(sb + SMG_TMEMP, 128);
        TC_RELINQ();
    }
    if (tid == 0) { MBAR_INIT(sb + SMG_MBAR, 1); }
    if (tid < 128) ((float*)(smem + SMG_BIAS))[tid] = bias[n0 + tid];

    const int nchunks = K >> 6;

#define STAGE_CHUNK(bsel, kc) do { \
    const int kel = (kc) * 64; \
    const uint32_t bbase = SMG_BUF0 + (bsel) * SMG_BUFSZ; \
    _Pragma("unroll") \
    for (int it = 0; it < 16; it++) { \
        int idx = it * 256 + tid; \
        int tile = idx >> 10; \
        int r = (idx >> 3) & 127; \
        int c16 = idx & 7; \
        uint4 val = make_uint4(0, 0, 0, 0); \
        if (tile < 2) { \
            int m = m0 + r; \
            if (m < M) { \
                const __nv_bfloat16* src = (tile == 0) ? Ahi : Alo; \
                val = *(const uint4*)&src[(size_t)m * K + kel + c16 * 8]; \
            } \
        } else { \
            int n = n0 + r; \
            const __nv_bfloat16* src = (tile == 2) ? Whi : Wlo; \
            val = *(const uint4*)&src[(size_t)n * K + kel + c16 * 8]; \
        } \
        uint32_t off = bbase + tile * 16384 + SW128((uint32_t)(r * 128 + c16 * 16)); \
        *(uint4*)(smem + off) = val; \
    } \
} while (0)

    STAGE_CHUNK(0, 0);
    __syncthreads();

    uint32_t tmem;
    asm volatile("ld.shared.b32 %0, [%1];" : "=r"(tmem) : "r"(sb + SMG_TMEMP));

    int phase = 0;
    for (int kc = 0; kc < nchunks; kc++) {
        const int bsel = kc & 1;
        const uint32_t bbase = sb + SMG_BUF0 + bsel * SMG_BUFSZ;
        if (wid == 0) {
            if (elect_one()) {
                FENCE_ASYNC();
                const uint64_t dAhi = MK_DESC(bbase);
                const uint64_t dAlo = MK_DESC(bbase + 16384);
                const uint64_t dBhi = MK_DESC(bbase + 32768);
                const uint64_t dBlo = MK_DESC(bbase + 49152);
                bool first = (kc == 0);
#pragma unroll
                for (int ks = 0; ks < 4; ks++)
                    mma_f16_ss(tmem, dAhi + ks * 2, dBhi + ks * 2, TC_IDESC, !(first && ks == 0));
#pragma unroll
                for (int ks = 0; ks < 4; ks++)
                    mma_f16_ss(tmem, dAhi + ks * 2, dBlo + ks * 2, TC_IDESC, true);
#pragma unroll
                for (int ks = 0; ks < 4; ks++)
                    mma_f16_ss(tmem, dAlo + ks * 2, dBhi + ks * 2, TC_IDESC, true);
                TC_COMMIT(sb + SMG_MBAR);
            }
        }
        if (kc + 1 < nchunks) {
            STAGE_CHUNK((kc + 1) & 1, kc + 1);
        }
        MBAR_WAIT(sb + SMG_MBAR, phase);
        phase ^= 1;
        __syncthreads();
    }
#undef STAGE_CHUNK

    TC_FENCE_AFTER();

    if (wid < 4) {
        const float* bsm = (const float*)(smem + SMG_BIAS);
        const int m = m0 + wid * 32 + lane;
#pragma unroll
        for (int cc = 0; cc < 4; cc++) {
            uint32_t dr[32];
            TC_LD_X32(dr, tmem + cc * 32);
            TC_WAIT_LD();
            if (m < M) {
                const int nb = n0 + cc * 32;
                if (SPLIT) {
#pragma unroll
                    for (int j2 = 0; j2 < 16; j2++) {
                        float v0 = __uint_as_float(dr[j2 * 2 + 0]) + bsm[cc * 32 + j2 * 2 + 0];
                        float v1 = __uint_as_float(dr[j2 * 2 + 1]) + bsm[cc * 32 + j2 * 2 + 1];
                        if (RELU) { v0 = fmaxf(v0, 0.f); v1 = fmaxf(v1, 0.f); }
                        __nv_bfloat16 h0 = __float2bfloat16_rn(v0);
                        __nv_bfloat16 h1 = __float2bfloat16_rn(v1);
                        __nv_bfloat16 l0 = __float2bfloat16_rn(v0 - __bfloat162float(h0));
                        __nv_bfloat16 l1 = __float2bfloat16_rn(v1 - __bfloat162float(h1));
                        *(__nv_bfloat162*)&Chi[(size_t)m * N + nb + j2 * 2] = __nv_bfloat162(h0, h1);
                        *(__nv_bfloat162*)&Clo[(size_t)m * N + nb + j2 * 2] = __nv_bfloat162(l0, l1);
                    }
                } else {
                    float* crow = &C[(size_t)m * N + nb];
#pragma unroll
                    for (int c4 = 0; c4 < 8; c4++) {
                        float4 o;
                        o.x = __uint_as_float(dr[c4 * 4 + 0]) + bsm[cc * 32 + c4 * 4 + 0];
                        o.y = __uint_as_float(dr[c4 * 4 + 1]) + bsm[cc * 32 + c4 * 4 + 1];
                        o.z = __uint_as_float(dr[c4 * 4 + 2]) + bsm[cc * 32 + c4 * 4 + 2];
                        o.w = __uint_as_float(dr[c4 * 4 + 3]) + bsm[cc * 32 + c4 * 4 + 3];
                        if (RELU) {
                            o.x = fmaxf(o.x, 0.f); o.y = fmaxf(o.y, 0.f);
                            o.z = fmaxf(o.z, 0.f); o.w = fmaxf(o.w, 0.f);
                        }
                        *(float4*)&crow[c4 * 4] = o;
                    }
                }
            }
        }
    }

    __syncthreads();
    if (wid == 0) { TC_DEALLOC(tmem, 128); }
#else
    // generic-PTX fallback (insurance)
    const int half = tid >> 7;
    const int m = m0 + (tid & 127);
    if (m < M) {
        for (int cg = half * 2; cg < half * 2 + 2; cg++) {
            float acc[32];
#pragma unroll
            for (int j = 0; j < 32; j++) acc[j] = bias[n0 + cg * 32 + j];
            for (int k = 0; k < K; k++) {
                float a = __bfloat162float(Ahi[(size_t)m * K + k]) +
                          __bfloat162float(Alo[(size_t)m * K + k]);
#pragma unroll
                for (int j = 0; j < 32; j++) {
                    int n = n0 + cg * 32 + j;
                    float w = __bfloat162float(Whi[(size_t)n * K + k]) +
                              __bfloat162float(Wlo[(size_t)n * K + k]);
                    acc[j] += a * w;
                }
            }
#pragma unroll
            for (int j = 0; j < 32; j++) {
                float v = acc[j];
                if (RELU) v = fmaxf(v, 0.f);
                int n = n0 + cg * 32 + j;
                if (SPLIT) {
                    __nv_bfloat16 h = __float2bfloat16_rn(v);
                    Chi[(size_t)m * N + n] = h;
                    Clo[(size_t)m * N + n] = __float2bfloat16_rn(v - __bfloat162float(h));
                } else {
                    C[(size_t)m * N + n] = v;
                }
            }
        }
    }
#endif
}

// ================= mega split =================
struct SplitArgs {
    const float* src[10];
    __nv_bfloat16* hi[10];
    __nv_bfloat16* lo[10];
    float* cpy[10];
    long long cum[11];
};

__global__ void mega_split_kernel(SplitArgs a) {
    long long i = (long long)blockIdx.x * blockDim.x + threadIdx.x;
    if (i >= a.cum[10]) return;
    int s = 0;
#pragma unroll
    for (int k = 0; k < 10; k++)
        if (i >= a.cum[k + 1]) s = k + 1;
    long long off = i - a.cum[s];
    float v = a.src[s][off];
    __nv_bfloat16 h = __float2bfloat16_rn(v);
    a.hi[s][off] = h;
    a.lo[s][off] = __float2bfloat16_rn(v - __bfloat162float(h));
    if (a.cpy[s]) a.cpy[s][off] = v;
}

// ================= unified tiled flash attention (SA + CA) =================
__global__ void __launch_bounds__(256, 2)
flash_attn_kernel(const float* __restrict__ Qp, int qstride,
                  const float* __restrict__ Kp, const float* __restrict__ Vp, int kvstride,
                  int nq, int nk,
                  const int* __restrict__ mask,
                  __nv_bfloat16* __restrict__ ohi, __nv_bfloat16* __restrict__ olo) {
    const int qt = blockIdx.x, h = blockIdx.y, b = blockIdx.z;
    const int tid = threadIdx.x;
    const int w = tid >> 5, lane = tid & 31;

    __shared__ __align__(16) float Ks[CK * 36];
    __shared__ __align__(16) float Vs[CK * 36];
    __shared__ __align__(16) float Qs[TQ * 36];
    __shared__ __align__(16) float Psm[8][4][CK];

    for (int i = tid; i < TQ * 8; i += 256) {
        int ql = i >> 3, d4 = i & 7;
        int qg = qt * TQ + ql;
        if (qg >= nq) qg = nq - 1;
        *(float4*)&Qs[ql * 36 + d4 * 4] =
            *(const float4*)&Qp[((size_t)(b * nq + qg)) * qstride + h * D + d4 * 4];
    }
    __syncthreads();

    int qg_[4];
    const int* mrow[4];
#pragma unroll
    for (int sub = 0; sub < 4; sub++) {
        int qg = qt * TQ + w * 4 + sub;
        qg_[sub] = qg;
        int qc = (qg < nq) ? qg : nq - 1;
        mrow[sub] = mask ? (mask + ((size_t)(b * nq + qc)) * nk) : nullptr;
    }

    float mv[4] = {-INFINITY, -INFINITY, -INFINITY, -INFINITY};
    float sv[4] = {0.f, 0.f, 0.f, 0.f};
    float2 av2[4] = {{0.f, 0.f}, {0.f, 0.f}, {0.f, 0.f}, {0.f, 0.f}};

    for (int k0 = 0; k0 < nk; k0 += CK) {
        // ---- mask prefetch (overlaps with K/V staging latency) ----
        int mk4[4][4];
        if (mask) {
#pragma unroll
            for (int c = 0; c < 4; c++) {
                int key = k0 + c * 32 + lane;
                bool kval = (key < nk);
#pragma unroll
                for (int sub = 0; sub < 4; sub++)
                    mk4[sub][c] = kval ? mrow[sub][key] : 0;
            }
        }

        // ---- stage K,V ----
        for (int i = tid; i < CK * 8; i += 256) {
            int j = i >> 3, d4 = i & 7;
            int kg = k0 + j;
            float4 kv = make_float4(0.f, 0.f, 0.f, 0.f);
            float4 vv = make_float4(0.f, 0.f, 0.f, 0.f);
            if (kg < nk) {
                size_t base = ((size_t)(b * nk + kg)) * kvstride + h * D + d4 * 4;
                kv = *(const float4*)&Kp[base];
                vv = *(const float4*)&Vp[base];
            }
            *(float4*)&Ks[j * 36 + d4 * 4] = kv;
            *(float4*)&Vs[j * 36 + d4 * 4] = vv;
        }
        __syncthreads();

        // ---- score phase ----
        float sc[4][4];
#pragma unroll
        for (int c = 0; c < 4; c++) {
            const int key = c * 32 + lane;
            const bool kval = (k0 + key < nk);
            float4 k4[8];
#pragma unroll
            for (int d4 = 0; d4 < 8; d4++)
                k4[d4] = *(const float4*)&Ks[key * 36 + d4 * 4];
#pragma unroll
            for (int sub = 0; sub < 4; sub++) {
                const int ql = w * 4 + sub;
                float2 s2 = make_float2(0.f, 0.f);
#pragma unroll
                for (int d4 = 0; d4 < 8; d4++) {
                    float4 q4 = *(const float4*)&Qs[ql * 36 + d4 * 4];
                    s2 = ffma2(make_float2(k4[d4].x, k4[d4].y), make_float2(q4.x, q4.y), s2);
                    s2 = ffma2(make_float2(k4[d4].z, k4[d4].w), make_float2(q4.z, q4.w), s2);
                }
                float s = s2.x + s2.y;
                bool val = kval && (!mask || (mk4[sub][c] != 0));
                sc[sub][c] = val ? (s * ATTN_SCALE) : -INFINITY;
            }
        }

        // ---- online softmax ----
#pragma unroll
        for (int sub = 0; sub < 4; sub++) {
            float cmax = fmaxf(fmaxf(sc[sub][0], sc[sub][1]), fmaxf(sc[sub][2], sc[sub][3]));
#pragma unroll
            for (int o = 16; o > 0; o >>= 1)
                cmax = fmaxf(cmax, __shfl_xor_sync(0xffffffff, cmax, o));
            float mOld = mv[sub];
            float mNew = fmaxf(mOld, cmax);
            float factor, psum = 0.f;
            if (mNew == -INFINITY) {
                factor = 1.f;
#pragma unroll
                for (int c = 0; c < 4; c++) Psm[w][sub][c * 32 + lane] = 0.f;
            } else {
                factor = __expf(mOld - mNew);
#pragma unroll
                for (int c = 0; c < 4; c++) {
                    float p = __expf(sc[sub][c] - mNew);   // exp(-inf)=0
                    psum += p;
                    Psm[w][sub][c * 32 + lane] = p;
                }
            }
#pragma unroll
            for (int o = 16; o > 0; o >>= 1)
                psum += __shfl_xor_sync(0xffffffff, psum, o);
            sv[sub] = sv[sub] * factor + psum;
            mv[sub] = mNew;
            av2[sub].x *= factor;
            av2[sub].y *= factor;
        }
        __syncwarp();

        // ---- V phase ----
#pragma unroll 4
        for (int j4 = 0; j4 < 32; j4++) {
            float v0 = Vs[(j4 * 4 + 0) * 36 + lane];
            float v1 = Vs[(j4 * 4 + 1) * 36 + lane];
            float v2 = Vs[(j4 * 4 + 2) * 36 + lane];
            float v3 = Vs[(j4 * 4 + 3) * 36 + lane];
#pragma unroll
            for (int sub = 0; sub < 4; sub++) {
                float4 p = *(const float4*)&Psm[w][sub][j4 * 4];
                av2[sub] = ffma2(make_float2(p.x, p.y), make_float2(v0, v1), av2[sub]);
                av2[sub] = ffma2(make_float2(p.z, p.w), make_float2(v2, v3), av2[sub]);
            }
        }
        __syncthreads();
    }

#pragma unroll
    for (int sub = 0; sub < 4; sub++) {
        if (qg_[sub] < nq) {
            float a = av2[sub].x + av2[sub].y;
            float inv = (sv[sub] > 0.f) ? 1.f / sv[sub] : 0.f;
            float o = a * inv;
            size_t idx = (size_t)(b * nq + qg_[sub]) * E + h * D + lane;
            __nv_bfloat16 hh = __float2bfloat16_rn(o);
            ohi[idx] = hh;
            olo[idx] = __float2bfloat16_rn(o - __bfloat162float(hh));
        }
    }
}

// ================= LayerNorm =================
__global__ void ln_kernel(const float* __restrict__ x,
                          const float* __restrict__ res,
                          const float* __restrict__ gamma,
                          const float* __restrict__ beta,
                          float* __restrict__ out,
                          __nv_bfloat16* __restrict__ ohi,
                          __nv_bfloat16* __restrict__ olo) {
    const int row = blockIdx.x;
    const int tid = threadIdx.x;
    const int lane = tid & 31, wid = tid >> 5;
    __shared__ float r1[8], r2[8];

    size_t idx = (size_t)row * E + tid;
    float v = x[idx];
    if (res) v += res[idx];

    float s = v;
#pragma unroll
    for (int o = 16; o > 0; o >>= 1) s += __shfl_xor_sync(0xffffffff, s, o);
    if (lane == 0) r1[wid] = s;
    __syncthreads();
    float tot = 0.f;
#pragma unroll
    for (int i = 0; i < 8; i++) tot += r1[i];
    float mean = tot * (1.f / E);

    float d = v - mean;
    float s2 = d * d;
#pragma unroll
    for (int o = 16; o > 0; o >>= 1) s2 += __shfl_xor_sync(0xffffffff, s2, o);
    if (lane == 0) r2[wid] = s2;
    __syncthreads();
    float tv = 0.f;
#pragma unroll
    for (int i = 0; i < 8; i++) tv += r2[i];
    float o_ = d * rsqrtf(tv * (1.f / E) + 1e-5f) * gamma[tid] + beta[tid];
    out[idx] = o_;
    if (ohi) {
        __nv_bfloat16 h = __float2bfloat16_rn(o_);
        ohi[idx] = h;
        olo[idx] = __float2bfloat16_rn(o_ - __bfloat162float(h));
    }
}

// ================= host side =================
static inline void tc_gemm(const __nv_bfloat16* Ahi, const __nv_bfloat16* Alo,
                           const __nv_bfloat16* Whi, const __nv_bfloat16* Wlo,
                           const float* bias, float* C, int M, int N, int K) {
    dim3 grid(N / 128, (M + 127) / 128, 1);
    tc_gemm_kernel<0, 0><<<grid, 256, SMG_TOTAL>>>(Ahi, Alo, Whi, Wlo, bias, C, nullptr, nullptr,
                                                   M, N, K, 0, 0, 0);
}
static inline void tc_gemm_batched(const __nv_bfloat16* Ahi, const __nv_bfloat16* Alo,
                                   const __nv_bfloat16* Whi, const __nv_bfloat16* Wlo,
                                   const float* bias, float* C, int M, int N, int K, int L,
                                   size_t wStride, size_t biasStride, size_t cStride) {
    dim3 grid(N / 128, (M + 127) / 128, L);
    tc_gemm_kernel<0, 0><<<grid, 256, SMG_TOTAL>>>(Ahi, Alo, Whi, Wlo, bias, C, nullptr, nullptr,
                                                   M, N, K, wStride, biasStride, cStride);
}
static inline void tc_gemm_relu_split(const __nv_bfloat16* Ahi, const __nv_bfloat16* Alo,
                                      const __nv_bfloat16* Whi, const __nv_bfloat16* Wlo,
                                      const float* bias, __nv_bfloat16* Chi, __nv_bfloat16* Clo,
                                      int M, int N, int K) {
    dim3 grid(N / 128, (M + 127) / 128, 1);
    tc_gemm_kernel<1, 1><<<grid, 256, SMG_TOTAL>>>(Ahi, Alo, Whi, Wlo, bias, nullptr, Chi, Clo,
                                                   M, N, K, 0, 0, 0);
}

extern "C" void kernel_launch(void* const* d_in, const int* in_sizes, int n_in,
                              void* d_out, int out_size) {
    cudaFuncSetAttribute(tc_gemm_kernel<0, 0>, cudaFuncAttributeMaxDynamicSharedMemorySize, SMG_TOTAL);
    cudaFuncSetAttribute(tc_gemm_kernel<1, 1>, cudaFuncAttributeMaxDynamicSharedMemorySize, SMG_TOTAL);

    const float* tgt      = (const float*)d_in[0];
    const float* memory   = (const float*)d_in[1];
    const int*   gmask    = (const int*)d_in[2];
    const float* sa_wqkv  = (const float*)d_in[3];
    const float* sa_bqkv  = (const float*)d_in[4];
    const float* sa_wo    = (const float*)d_in[5];
    const float* sa_bo    = (const float*)d_in[6];
    const float* ca_wq    = (const float*)d_in[7];
    const float* ca_bq    = (const float*)d_in[8];
    const float* ca_wk    = (const float*)d_in[9];
    const float* ca_bk    = (const float*)d_in[10];
    const float* ca_wv    = (const float*)d_in[11];
    const float* ca_bv    = (const float*)d_in[12];
    const float* ca_wo    = (const float*)d_in[13];
    const float* ca_bo    = (const float*)d_in[14];
    const float* f_w1     = (const float*)d_in[15];
    const float* f_b1     = (const float*)d_in[16];
    const float* f_w2     = (const float*)d_in[17];
    const float* f_b2     = (const float*)d_in[18];
    const float* ln1g     = (const float*)d_in[19];
    const float* ln1b     = (const float*)d_in[20];
    const float* ln2g     = (const float*)d_in[21];
    const float* ln2b     = (const float*)d_in[22];
    const float* ln3g     = (const float*)d_in[23];
    const float* ln3b     = (const float*)d_in[24];
    const float* lnfg     = (const float*)d_in[25];
    const float* lnfb     = (const float*)d_in[26];

    float *t, *qkv, *proj, *qb, *k6, *v6;
    cudaGetSymbolAddress((void**)&t,    g_t);
    cudaGetSymbolAddress((void**)&qkv,  g_qkv);
    cudaGetSymbolAddress((void**)&proj, g_proj);
    cudaGetSymbolAddress((void**)&qb,   g_q);
    cudaGetSymbolAddress((void**)&k6,   g_k6);
    cudaGetSymbolAddress((void**)&v6,   g_v6);

    __nv_bfloat16 *whi, *wlo, *thi, *tlo, *ahi, *alo, *mhi, *mlo, *fhi, *flo;
    cudaGetSymbolAddress((void**)&whi, g_whi);
    cudaGetSymbolAddress((void**)&wlo, g_wlo);
    cudaGetSymbolAddress((void**)&thi, g_thi);
    cudaGetSymbolAddress((void**)&tlo, g_tlo);
    cudaGetSymbolAddress((void**)&ahi, g_ahi);
    cudaGetSymbolAddress((void**)&alo, g_alo);
    cudaGetSymbolAddress((void**)&mhi, g_mhi);
    cudaGetSymbolAddress((void**)&mlo, g_mlo);
    cudaGetSymbolAddress((void**)&fhi, g_fhi);
    cudaGetSymbolAddress((void**)&flo, g_flo);

    // ---- one mega split launch ----
    {
        SplitArgs a;
        const float* srcs[10] = {sa_wqkv, sa_wo, ca_wq, ca_wk, ca_wv, ca_wo, f_w1, f_w2, memory, tgt};
        long long sizes[10] = {
            (long long)LAYERS * 3 * E * E, (long long)LAYERS * E * E, (long long)LAYERS * E * E,
            (long long)LAYERS * E * E, (long long)LAYERS * E * E, (long long)LAYERS * E * E,
            (long long)LAYERS * FF * E, (long long)LAYERS * E * FF,
            (long long)MK_ROWS * E, (long long)MQ_ROWS * E};
        long long offs[8] = {OFF_WQKV, OFF_WO, OFF_WQ, OFF_WK, OFF_WV, OFF_WCO, OFF_W1, OFF_W2};
        a.cum[0] = 0;
        for (int s = 0; s < 10; s++) {
            a.src[s] = srcs[s];
            a.cpy[s] = nullptr;
            a.cum[s + 1] = a.cum[s] + sizes[s];
            if (s < 8)       { a.hi[s] = whi + offs[s]; a.lo[s] = wlo + offs[s]; }
            else if (s == 8) { a.hi[s] = mhi;           a.lo[s] = mlo; }
            else             { a.hi[s] = thi;           a.lo[s] = tlo; a.cpy[s] = t; }
        }
        long long total = a.cum[10];
        mega_split_kernel<<<(unsigned)((total + 255) / 256), 256>>>(a);
    }

    // ---- precompute ALL layers' CA K/V projections in 2 batched launches ----
    tc_gemm_batched(mhi, mlo, whi + OFF_WK, wlo + OFF_WK, ca_bk, k6,
                    MK_ROWS, E, E, LAYERS, (size_t)E * E, E, (size_t)MK_ROWS * E);
    tc_gemm_batched(mhi, mlo, whi + OFF_WV, wlo + OFF_WV, ca_bv, v6,
                    MK_ROWS, E, E, LAYERS, (size_t)E * E, E, (size_t)MK_ROWS * E);

    dim3 attn_grid((NQ + TQ - 1) / TQ, H, B);

    for (int l = 0; l < LAYERS; l++) {
        const size_t wEE = (size_t)l * E * E;
        const __nv_bfloat16* wqkv_h = whi + OFF_WQKV + (size_t)l * 3 * E * E;
        const __nv_bfloat16* wqkv_l = wlo + OFF_WQKV + (size_t)l * 3 * E * E;
        const float* bqkv = sa_bqkv + (size_t)l * 3 * E;
        const float* bo   = sa_bo + (size_t)l * E;
        const float* bq   = ca_bq + (size_t)l * E;
        const float* bco  = ca_bo + (size_t)l * E;
        const float* b1   = f_b1 + (size_t)l * FF;
        const float* b2   = f_b2 + (size_t)l * E;
        const float* g1   = ln1g + (size_t)l * E;
        const float* be1  = ln1b + (size_t)l * E;
        const float* g2   = ln2g + (size_t)l * E;
        const float* be2  = ln2b + (size_t)l * E;
        const float* g3   = ln3g + (size_t)l * E;
        const float* be3  = ln3b + (size_t)l * E;

        float* kb = k6 + (size_t)l * MK_ROWS * E;
        float* vb = v6 + (size_t)l * MK_ROWS * E;

        // --- self-attention ---
        tc_gemm(thi, tlo, wqkv_h, wqkv_l, bqkv, qkv, MQ_ROWS, 3 * E, E);
        flash_attn_kernel<<<attn_grid, 256>>>(qkv, 3 * E, qkv + E, qkv + 2 * E, 3 * E,
                                              NQ, NQ, nullptr, ahi, alo);
        tc_gemm(ahi, alo, whi + OFF_WO + wEE, wlo + OFF_WO + wEE, bo, proj, MQ_ROWS, E, E);
        ln_kernel<<<MQ_ROWS, E>>>(t, proj, g1, be1, t, thi, tlo);

        // --- cross-attention ---
        tc_gemm(thi, tlo, whi + OFF_WQ + wEE, wlo + OFF_WQ + wEE, bq, qb, MQ_ROWS, E, E);
        flash_attn_kernel<<<attn_grid, 256>>>(qb, E, kb, vb, E,
                                              NQ, NK, gmask, ahi, alo);
        tc_gemm(ahi, alo, whi + OFF_WCO + wEE, wlo + OFF_WCO + wEE, bco, proj, MQ_ROWS, E, E);
        ln_kernel<<<MQ_ROWS, E>>>(t, proj, g2, be2, t, thi, tlo);

        // --- FFN ---
        tc_gemm_relu_split(thi, tlo, whi + OFF_W1 + (size_t)l * FF * E, wlo + OFF_W1 + (size_t)l * FF * E,
                           b1, fhi, flo, MQ_ROWS, FF, E);
        tc_gemm(fhi, flo, whi + OFF_W2 + (size_t)l * E * FF, wlo + OFF_W2 + (size_t)l * E * FF,
                b2, proj, MQ_ROWS, E, FF);
        ln_kernel<<<MQ_ROWS, E>>>(t, proj, g3, be3, t, thi, tlo);
    }

    ln_kernel<<<MQ_ROWS, E>>>(t, nullptr, lnfg, lnfb, (float*)d_out, nullptr, nullptr);
}